// round 9
// baseline (speedup 1.0000x reference)
#include <cuda_runtime.h>
#include <cuda_fp16.h>
#include <cstdint>
#include <math.h>

#define NN 10000
#define NE 320000
#define NH 128
#define NPAD 10112            // 79 * 128
#define TS_STRIDE 129
#define XT_STRIDE 136         // f16 tile stride: 272B/row == 16 mod 128 -> conflict-free
#define RS (XT_STRIDE * 2)

// ---------------- scratch ----------------------------------------------------
__device__ float g_hw[(size_t)NN * NH];
__device__ __half g_y[(size_t)NPAD * NH];    // fp16(x), zero-padded
__device__ int g_deg[NN];
__device__ int g_off[NN + 1];
__device__ int g_fill[NN];
__device__ int g_csr[NE];

// ============================================================================
// CSR build (count / scan / fill) — zero is fused into hw-gemm launch
__global__ void csr_count_kernel(const int* __restrict__ ed) {
    int e = blockIdx.x * 256 + threadIdx.x;
    if (e < NE) atomicAdd(&g_deg[ed[e]], 1);
}
__global__ void csr_scan_kernel() {
    __shared__ int part[1024];
    int tid = threadIdx.x;
    int base = tid * 10;
    int s = 0;
    #pragma unroll
    for (int q = 0; q < 10; ++q) { int i = base + q; if (i < NN) s += g_deg[i]; }
    part[tid] = s;
    __syncthreads();
    #pragma unroll
    for (int off = 1; off < 1024; off <<= 1) {
        int v = (tid >= off) ? part[tid - off] : 0;
        __syncthreads();
        part[tid] += v;
        __syncthreads();
    }
    int run = (tid == 0) ? 0 : part[tid - 1];
    #pragma unroll
    for (int q = 0; q < 10; ++q) {
        int i = base + q;
        if (i < NN) { g_off[i] = run; run += g_deg[i]; }
    }
    if (tid == 0) g_off[NN] = part[1023];
}
__global__ void csr_fill_kernel(const int* __restrict__ es,
                                const int* __restrict__ ed) {
    int e = blockIdx.x * 256 + threadIdx.x;
    if (e < NE) {
        int d = ed[e];
        int pos = atomicAdd(&g_fill[d], 1);
        g_csr[g_off[d] + pos] = es[e];
    }
}

// ============================================================================
// hw = h @ W (fp32 SIMT, 512 threads/block) + fused CSR-counter zeroing.
// Blocks [0,79): 128-row GEMM stripes. Blocks [79,119): zero g_deg/g_fill.
#define HW_BLOCKS 79
#define ZERO_BLOCKS 40
extern "C" __global__ void __launch_bounds__(512)
gemm_hw_zero_kernel(const float* __restrict__ h, const float* __restrict__ W) {
    if (blockIdx.x >= HW_BLOCKS) {
        int idx = (blockIdx.x - HW_BLOCKS) * 512 + threadIdx.x;   // < 20480
        if (idx < NN) g_deg[idx] = 0;
        else if (idx < 2 * NN) g_fill[idx - NN] = 0;
        return;
    }
    extern __shared__ float smemf[];
    float* As = smemf;                        // [k][m] 128 x 129
    float* Bs = smemf + 128 * TS_STRIDE;      // [k][n] 128 x 129
    int row0 = blockIdx.x * 128;
    {   // load h tile transposed: 16 warps x 8 rows
        int lane = threadIdx.x & 31, w = threadIdx.x >> 5;
        #pragma unroll
        for (int rr = 0; rr < 8; ++rr) {
            int r = w * 8 + rr;
            bool ok = (row0 + r < NN);
            const float* p = h + (size_t)(row0 + r) * NH;
            #pragma unroll
            for (int q = 0; q < 4; ++q) {
                int k = lane + 32 * q;
                As[k * TS_STRIDE + r] = ok ? p[k] : 0.0f;
            }
        }
        #pragma unroll
        for (int rr = 0; rr < 8; ++rr) {
            int k = w * 8 + rr;
            #pragma unroll
            for (int q = 0; q < 4; ++q) {
                int n = lane + 32 * q;
                Bs[k * TS_STRIDE + n] = W[k * NH + n];
            }
        }
    }
    __syncthreads();
    int tx = threadIdx.x & 15;       // col group: n = tx + 16j, j<8
    int ty = threadIdx.x >> 4;       // row group: m = ty + 32i, i<4
    float acc[4][8] = {};
    #pragma unroll 8
    for (int k = 0; k < 128; ++k) {
        float a[4], b[8];
        #pragma unroll
        for (int i = 0; i < 4; ++i) a[i] = As[k * TS_STRIDE + ty + 32 * i];
        #pragma unroll
        for (int j = 0; j < 8; ++j) b[j] = Bs[k * TS_STRIDE + tx + 16 * j];
        #pragma unroll
        for (int i = 0; i < 4; ++i)
            #pragma unroll
            for (int j = 0; j < 8; ++j)
                acc[i][j] = fmaf(a[i], b[j], acc[i][j]);
    }
    #pragma unroll
    for (int i = 0; i < 4; ++i) {
        int m = row0 + ty + 32 * i;
        if (m < NN)
            #pragma unroll
            for (int j = 0; j < 8; ++j)
                g_hw[(size_t)m * NH + tx + 16 * j] = acc[i][j];
    }
}

// ============================================================================
// fused gather + bias + relu + fp16 quantize (one block per row)
extern "C" __global__ void gather_fuse_kernel(const float* __restrict__ b) {
    int node = blockIdx.x;
    int c = threadIdx.x;
    size_t o = (size_t)node * NH + c;
    if (node >= NN) { g_y[o] = __float2half(0.0f); return; }
    int beg = g_off[node];
    int end = g_off[node + 1];
    float acc = 0.0f;
    int e = beg;
    for (; e + 4 <= end; e += 4) {
        int s0 = g_csr[e], s1 = g_csr[e + 1], s2 = g_csr[e + 2], s3 = g_csr[e + 3];
        float v0 = g_hw[(size_t)s0 * NH + c];
        float v1 = g_hw[(size_t)s1 * NH + c];
        float v2 = g_hw[(size_t)s2 * NH + c];
        float v3 = g_hw[(size_t)s3 * NH + c];
        acc += (v0 + v1) + (v2 + v3);
    }
    for (; e < end; ++e)
        acc += g_hw[(size_t)g_csr[e] * NH + c];
    float v = acc + b[c];
    v = v > 0.0f ? v : 0.0f;
    g_y[o] = __float2half_rn(v);
}

// ============================================================================
// xxt = y @ y^T, single fp16 HMMA pass, f32 acc, triangular grid, .cs stores
#define TILE_BYTES (128 * RS)                 // 34816
#define SMEM_XXT_BYTES (2 * TILE_BYTES)       // 69632 -> occ 2

__device__ __forceinline__ uint32_t smem_u32_of(const void* p) {
    uint32_t a;
    asm("{ .reg .u64 t; cvta.to.shared.u64 t, %1; cvt.u32.u64 %0, t; }"
        : "=r"(a) : "l"(p));
    return a;
}
__device__ __forceinline__ void ldsm_x4(uint32_t r[4], uint32_t addr) {
    asm volatile("ldmatrix.sync.aligned.m8n8.x4.shared.b16 {%0,%1,%2,%3}, [%4];"
                 : "=r"(r[0]), "=r"(r[1]), "=r"(r[2]), "=r"(r[3]) : "r"(addr));
}
__device__ __forceinline__ void cp16(uint32_t dst, const void* src) {
    asm volatile("cp.async.cg.shared.global [%0], [%1], 16;" :: "r"(dst), "l"(src));
}
#define CP_COMMIT() asm volatile("cp.async.commit_group;" ::: "memory")
#define CP_WAIT()   asm volatile("cp.async.wait_all;" ::: "memory")

__device__ __forceinline__ void load_tile_async(const __half* __restrict__ src,
                                                int row0, uint32_t dst) {
    int tid = threadIdx.x;  // 256 threads, 8 x 16B each
    #pragma unroll
    for (int it = 0; it < 8; ++it) {
        int chunk = it * 256 + tid;
        int row = chunk >> 4, c16 = chunk & 15;
        cp16(dst + row * RS + c16 * 16,
             src + (size_t)(row0 + row) * NH + c16 * 8);
    }
}
__device__ __forceinline__ void mma_f32acc(float d[4], const uint32_t a[4],
                                           uint32_t b0, uint32_t b1) {
    asm volatile(
        "mma.sync.aligned.m16n8k16.row.col.f32.f16.f16.f32 "
        "{%0,%1,%2,%3}, {%4,%5,%6,%7}, {%8,%9}, {%0,%1,%2,%3};"
        : "+f"(d[0]), "+f"(d[1]), "+f"(d[2]), "+f"(d[3])
        : "r"(a[0]), "r"(a[1]), "r"(a[2]), "r"(a[3]), "r"(b0), "r"(b1));
}
__device__ __forceinline__ void stcs1(float* p, float v) {
    asm volatile("st.global.cs.f32 [%0], %1;" :: "l"(p), "f"(v) : "memory");
}
__device__ __forceinline__ void stcs2(float* p, float v0, float v1) {
    asm volatile("st.global.cs.v2.f32 [%0], {%1, %2};"
                 :: "l"(p), "f"(v0), "f"(v1) : "memory");
}

extern "C" __global__ void __launch_bounds__(256, 2)
xxt_mma_kernel(float* __restrict__ out) {
    // triangular decode: t -> (bym, bxn), bym <= bxn, 79x79 upper triangle
    int t = blockIdx.x;
    int r = (int)((159.0f - sqrtf(25281.0f - 8.0f * (float)t)) * 0.5f);
    if (r < 0) r = 0; if (r > 78) r = 78;
    while ((r + 1) * 79 - ((r + 1) * r) / 2 <= t) ++r;
    while (r * 79 - (r * (r - 1)) / 2 > t) --r;
    int bym = r;
    int bxn = r + (t - (r * 79 - (r * (r - 1)) / 2));
    bool diag = (bxn == bym);

    extern __shared__ char smem[];
    uint32_t uA = smem_u32_of(smem);
    uint32_t uB = uA + TILE_BYTES;

    load_tile_async(g_y, bym * 128, uA);
    if (!diag) load_tile_async(g_y, bxn * 128, uB);
    else       uB = uA;
    CP_COMMIT(); CP_WAIT();
    __syncthreads();

    int tid = threadIdx.x, lane = tid & 31, wid = tid >> 5;
    int wm = wid & 1;
    int wn = wid >> 1;
    int frow = lane >> 2;
    int fcol = 2 * (lane & 3);
    uint32_t laneA = (uint32_t)((lane & 15) * RS + (lane >> 4) * 16);
    uint32_t laneB = (uint32_t)((((lane >> 4) & 1) * 8 + (lane & 7)) * RS
                                + ((lane >> 3) & 1) * 16);

    float acc[4][4][4] = {};

    #pragma unroll
    for (int k0 = 0; k0 < 8; ++k0) {
        uint32_t kb = k0 * 32;
        uint32_t bf[2][4];
        #pragma unroll
        for (int jp = 0; jp < 2; ++jp)
            ldsm_x4(bf[jp], uB + laneB + (uint32_t)((wn * 32 + jp * 16) * RS) + kb);
        #pragma unroll
        for (int i = 0; i < 4; ++i) {
            uint32_t a[4];
            ldsm_x4(a, uA + laneA + (uint32_t)((wm * 64 + i * 16) * RS) + kb);
            #pragma unroll
            for (int jp = 0; jp < 2; ++jp) {
                mma_f32acc(acc[i][2 * jp],     a, bf[jp][0], bf[jp][1]);
                mma_f32acc(acc[i][2 * jp + 1], a, bf[jp][2], bf[jp][3]);
            }
        }
    }

    int m0 = bym * 128, n0 = bxn * 128;
    bool edge = (n0 + 127 >= NN) || (m0 + 127 >= NN);

    // main-tile store C[m][n] (streaming float2)
    #pragma unroll
    for (int i = 0; i < 4; ++i) {
        int rr = wm * 64 + i * 16 + frow;
        #pragma unroll
        for (int j = 0; j < 4; ++j) {
            int c = wn * 32 + j * 8 + fcol;
            if (!edge) {
                stcs2(&out[(size_t)(m0 + rr) * NN + n0 + c],
                      acc[i][j][0], acc[i][j][1]);
                stcs2(&out[(size_t)(m0 + rr + 8) * NN + n0 + c],
                      acc[i][j][2], acc[i][j][3]);
            } else {
                int m1 = m0 + rr, m2 = m0 + rr + 8, n = n0 + c;
                if (m1 < NN) {
                    if (n < NN)     stcs1(&out[(size_t)m1 * NN + n],     acc[i][j][0]);
                    if (n + 1 < NN) stcs1(&out[(size_t)m1 * NN + n + 1], acc[i][j][1]);
                }
                if (m2 < NN) {
                    if (n < NN)     stcs1(&out[(size_t)m2 * NN + n],     acc[i][j][2]);
                    if (n + 1 < NN) stcs1(&out[(size_t)m2 * NN + n + 1], acc[i][j][3]);
                }
            }
        }
    }

    // mirror store C[n][m] directly from fragments (off-diagonal only)
    if (!diag) {
        bool nedge = (n0 + 127 >= NN);   // m side always interior (bym <= 77)
        #pragma unroll
        for (int i = 0; i < 4; ++i) {
            int rr = wm * 64 + i * 16 + frow;
            size_t m1 = (size_t)(m0 + rr);
            size_t m2 = (size_t)(m0 + rr + 8);
            #pragma unroll
            for (int j = 0; j < 4; ++j) {
                int c = wn * 32 + j * 8 + fcol;
                size_t n1 = (size_t)(n0 + c), n2 = (size_t)(n0 + c + 1);
                if (!nedge) {
                    stcs1(&out[n1 * NN + m1], acc[i][j][0]);
                    stcs1(&out[n2 * NN + m1], acc[i][j][1]);
                    stcs1(&out[n1 * NN + m2], acc[i][j][2]);
                    stcs1(&out[n2 * NN + m2], acc[i][j][3]);
                } else {
                    if (n1 < NN) { stcs1(&out[n1 * NN + m1], acc[i][j][0]);
                                   stcs1(&out[n1 * NN + m2], acc[i][j][2]); }
                    if (n2 < NN) { stcs1(&out[n2 * NN + m1], acc[i][j][1]);
                                   stcs1(&out[n2 * NN + m2], acc[i][j][3]); }
                }
            }
        }
    }
}

// ============================================================================
extern "C" void kernel_launch(void* const* d_in, const int* in_sizes, int n_in,
                              void* d_out, int out_size) {
    const float* h  = (const float*)d_in[0];
    const float* W  = (const float*)d_in[1];
    const float* b  = (const float*)d_in[2];
    const int*   es = (const int*)d_in[3];
    const int*   ed = (const int*)d_in[4];
    float*       out = (float*)d_out;

    const size_t smem_hw = (size_t)2 * 128 * TS_STRIDE * sizeof(float);
    cudaFuncSetAttribute(gemm_hw_zero_kernel,
                         cudaFuncAttributeMaxDynamicSharedMemorySize, (int)smem_hw);
    cudaFuncSetAttribute(xxt_mma_kernel,
                         cudaFuncAttributeMaxDynamicSharedMemorySize, SMEM_XXT_BYTES);

    // hw = h@W (blocks 0..78) and zero CSR counters (blocks 79..118), one launch
    gemm_hw_zero_kernel<<<HW_BLOCKS + ZERO_BLOCKS, 512, smem_hw>>>(h, W);
    csr_count_kernel<<<(NE + 255) / 256, 256>>>(ed);
    csr_scan_kernel<<<1, 1024>>>();
    csr_fill_kernel<<<(NE + 255) / 256, 256>>>(es, ed);
    gather_fuse_kernel<<<NPAD, 128>>>(b);
    xxt_mma_kernel<<<3160, 256, SMEM_XXT_BYTES>>>(out);
}

// round 10
// speedup vs baseline: 1.4548x; 1.4548x over previous
#include <cuda_runtime.h>
#include <cuda_fp16.h>
#include <cstdint>
#include <math.h>

#define NN 10000
#define NE 320000
#define NH 128
#define NPAD 10112            // 79 * 128
#define TS_STRIDE 129
#define XT_STRIDE 136         // f16 tile stride: 272B/row == 16 mod 128 -> conflict-free
#define RS (XT_STRIDE * 2)

// ---------------- scratch ----------------------------------------------------
__device__ float g_hw[(size_t)NN * NH];
__device__ __half g_y[(size_t)NPAD * NH];    // fp16(x), zero-padded
__device__ int g_deg[NN];
__device__ int g_off[NN + 1];
__device__ int g_fill[NN];
__device__ int g_csr[NE];

// ============================================================================
// CSR build (count / scan / fill) — zero is fused into hw-gemm launch
__global__ void csr_count_kernel(const int* __restrict__ ed) {
    int e = blockIdx.x * 256 + threadIdx.x;
    if (e < NE) atomicAdd(&g_deg[ed[e]], 1);
}
__global__ void csr_scan_kernel() {
    __shared__ int part[1024];
    int tid = threadIdx.x;
    int base = tid * 10;
    int s = 0;
    #pragma unroll
    for (int q = 0; q < 10; ++q) { int i = base + q; if (i < NN) s += g_deg[i]; }
    part[tid] = s;
    __syncthreads();
    #pragma unroll
    for (int off = 1; off < 1024; off <<= 1) {
        int v = (tid >= off) ? part[tid - off] : 0;
        __syncthreads();
        part[tid] += v;
        __syncthreads();
    }
    int run = (tid == 0) ? 0 : part[tid - 1];
    #pragma unroll
    for (int q = 0; q < 10; ++q) {
        int i = base + q;
        if (i < NN) { g_off[i] = run; run += g_deg[i]; }
    }
    if (tid == 0) g_off[NN] = part[1023];
}
__global__ void csr_fill_kernel(const int* __restrict__ es,
                                const int* __restrict__ ed) {
    int e = blockIdx.x * 256 + threadIdx.x;
    if (e < NE) {
        int d = ed[e];
        int pos = atomicAdd(&g_fill[d], 1);
        g_csr[g_off[d] + pos] = es[e];
    }
}

// ============================================================================
// hw = h @ W (fp32 SIMT, 512 threads/block) + fused CSR-counter zeroing.
#define HW_BLOCKS 79
#define ZERO_BLOCKS 40
extern "C" __global__ void __launch_bounds__(512)
gemm_hw_zero_kernel(const float* __restrict__ h, const float* __restrict__ W) {
    if (blockIdx.x >= HW_BLOCKS) {
        int idx = (blockIdx.x - HW_BLOCKS) * 512 + threadIdx.x;   // < 20480
        if (idx < NN) g_deg[idx] = 0;
        else if (idx < 2 * NN) g_fill[idx - NN] = 0;
        return;
    }
    extern __shared__ float smemf[];
    float* As = smemf;                        // [k][m] 128 x 129
    float* Bs = smemf + 128 * TS_STRIDE;      // [k][n] 128 x 129
    int row0 = blockIdx.x * 128;
    {   // load h tile transposed: 16 warps x 8 rows
        int lane = threadIdx.x & 31, w = threadIdx.x >> 5;
        #pragma unroll
        for (int rr = 0; rr < 8; ++rr) {
            int r = w * 8 + rr;
            bool ok = (row0 + r < NN);
            const float* p = h + (size_t)(row0 + r) * NH;
            #pragma unroll
            for (int q = 0; q < 4; ++q) {
                int k = lane + 32 * q;
                As[k * TS_STRIDE + r] = ok ? p[k] : 0.0f;
            }
        }
        #pragma unroll
        for (int rr = 0; rr < 8; ++rr) {
            int k = w * 8 + rr;
            #pragma unroll
            for (int q = 0; q < 4; ++q) {
                int n = lane + 32 * q;
                Bs[k * TS_STRIDE + n] = W[k * NH + n];
            }
        }
    }
    __syncthreads();
    int tx = threadIdx.x & 15;       // col group: n = tx + 16j, j<8
    int ty = threadIdx.x >> 4;       // row group: m = ty + 32i, i<4
    float acc[4][8] = {};
    #pragma unroll 8
    for (int k = 0; k < 128; ++k) {
        float a[4], b[8];
        #pragma unroll
        for (int i = 0; i < 4; ++i) a[i] = As[k * TS_STRIDE + ty + 32 * i];
        #pragma unroll
        for (int j = 0; j < 8; ++j) b[j] = Bs[k * TS_STRIDE + tx + 16 * j];
        #pragma unroll
        for (int i = 0; i < 4; ++i)
            #pragma unroll
            for (int j = 0; j < 8; ++j)
                acc[i][j] = fmaf(a[i], b[j], acc[i][j]);
    }
    #pragma unroll
    for (int i = 0; i < 4; ++i) {
        int m = row0 + ty + 32 * i;
        if (m < NN)
            #pragma unroll
            for (int j = 0; j < 8; ++j)
                g_hw[(size_t)m * NH + tx + 16 * j] = acc[i][j];
    }
}

// ============================================================================
// fused gather + bias + relu + fp16 quantize (one block per row)
extern "C" __global__ void gather_fuse_kernel(const float* __restrict__ b) {
    int node = blockIdx.x;
    int c = threadIdx.x;
    size_t o = (size_t)node * NH + c;
    if (node >= NN) { g_y[o] = __float2half(0.0f); return; }
    int beg = g_off[node];
    int end = g_off[node + 1];
    float acc = 0.0f;
    int e = beg;
    for (; e + 4 <= end; e += 4) {
        int s0 = g_csr[e], s1 = g_csr[e + 1], s2 = g_csr[e + 2], s3 = g_csr[e + 3];
        float v0 = g_hw[(size_t)s0 * NH + c];
        float v1 = g_hw[(size_t)s1 * NH + c];
        float v2 = g_hw[(size_t)s2 * NH + c];
        float v3 = g_hw[(size_t)s3 * NH + c];
        acc += (v0 + v1) + (v2 + v3);
    }
    for (; e < end; ++e)
        acc += g_hw[(size_t)g_csr[e] * NH + c];
    float v = acc + b[c];
    v = v > 0.0f ? v : 0.0f;
    g_y[o] = __float2half_rn(v);
}

// ============================================================================
// xxt = y @ y^T, single fp16 HMMA pass, f32 acc, triangular grid (R8 stores)
#define TILE_BYTES (128 * RS)                 // 34816
#define SMEM_XXT_BYTES (2 * TILE_BYTES)       // 69632 -> occ 2

__device__ __forceinline__ uint32_t smem_u32_of(const void* p) {
    uint32_t a;
    asm("{ .reg .u64 t; cvta.to.shared.u64 t, %1; cvt.u32.u64 %0, t; }"
        : "=r"(a) : "l"(p));
    return a;
}
__device__ __forceinline__ void ldsm_x4(uint32_t r[4], uint32_t addr) {
    asm volatile("ldmatrix.sync.aligned.m8n8.x4.shared.b16 {%0,%1,%2,%3}, [%4];"
                 : "=r"(r[0]), "=r"(r[1]), "=r"(r[2]), "=r"(r[3]) : "r"(addr));
}
__device__ __forceinline__ void cp16(uint32_t dst, const void* src) {
    asm volatile("cp.async.cg.shared.global [%0], [%1], 16;" :: "r"(dst), "l"(src));
}
#define CP_COMMIT() asm volatile("cp.async.commit_group;" ::: "memory")
#define CP_WAIT()   asm volatile("cp.async.wait_all;" ::: "memory")

__device__ __forceinline__ void load_tile_async(const __half* __restrict__ src,
                                                int row0, uint32_t dst) {
    int tid = threadIdx.x;  // 256 threads, 8 x 16B each
    #pragma unroll
    for (int it = 0; it < 8; ++it) {
        int chunk = it * 256 + tid;
        int row = chunk >> 4, c16 = chunk & 15;
        cp16(dst + row * RS + c16 * 16,
             src + (size_t)(row0 + row) * NH + c16 * 8);
    }
}
__device__ __forceinline__ void mma_f32acc(float d[4], const uint32_t a[4],
                                           uint32_t b0, uint32_t b1) {
    asm volatile(
        "mma.sync.aligned.m16n8k16.row.col.f32.f16.f16.f32 "
        "{%0,%1,%2,%3}, {%4,%5,%6,%7}, {%8,%9}, {%0,%1,%2,%3};"
        : "+f"(d[0]), "+f"(d[1]), "+f"(d[2]), "+f"(d[3])
        : "r"(a[0]), "r"(a[1]), "r"(a[2]), "r"(a[3]), "r"(b0), "r"(b1));
}

extern "C" __global__ void __launch_bounds__(256, 2)
xxt_mma_kernel(float* __restrict__ out) {
    // triangular decode: t -> (bym, bxn), bym <= bxn, 79x79 upper triangle
    int t = blockIdx.x;
    int r = (int)((159.0f - sqrtf(25281.0f - 8.0f * (float)t)) * 0.5f);
    if (r < 0) r = 0; if (r > 78) r = 78;
    while ((r + 1) * 79 - ((r + 1) * r) / 2 <= t) ++r;
    while (r * 79 - (r * (r - 1)) / 2 > t) --r;
    int bym = r;
    int bxn = r + (t - (r * 79 - (r * (r - 1)) / 2));
    bool diag = (bxn == bym);

    extern __shared__ char smem[];
    uint32_t uA = smem_u32_of(smem);
    uint32_t uB = uA + TILE_BYTES;

    load_tile_async(g_y, bym * 128, uA);
    if (!diag) load_tile_async(g_y, bxn * 128, uB);
    else       uB = uA;
    CP_COMMIT(); CP_WAIT();
    __syncthreads();

    int tid = threadIdx.x, lane = tid & 31, wid = tid >> 5;
    int wm = wid & 1;
    int wn = wid >> 1;
    int frow = lane >> 2;
    int fcol = 2 * (lane & 3);
    uint32_t laneA = (uint32_t)((lane & 15) * RS + (lane >> 4) * 16);
    uint32_t laneB = (uint32_t)((((lane >> 4) & 1) * 8 + (lane & 7)) * RS
                                + ((lane >> 3) & 1) * 16);

    float acc[4][4][4] = {};

    #pragma unroll
    for (int k0 = 0; k0 < 8; ++k0) {
        uint32_t kb = k0 * 32;
        uint32_t bf[2][4];
        #pragma unroll
        for (int jp = 0; jp < 2; ++jp)
            ldsm_x4(bf[jp], uB + laneB + (uint32_t)((wn * 32 + jp * 16) * RS) + kb);
        #pragma unroll
        for (int i = 0; i < 4; ++i) {
            uint32_t a[4];
            ldsm_x4(a, uA + laneA + (uint32_t)((wm * 64 + i * 16) * RS) + kb);
            #pragma unroll
            for (int jp = 0; jp < 2; ++jp) {
                mma_f32acc(acc[i][2 * jp],     a, bf[jp][0], bf[jp][1]);
                mma_f32acc(acc[i][2 * jp + 1], a, bf[jp][2], bf[jp][3]);
            }
        }
    }

    int m0 = bym * 128, n0 = bxn * 128;
    bool edge = (n0 + 127 >= NN) || (m0 + 127 >= NN);

    // main-tile store C[m][n] (float2, default policy — L2 write-combines)
    #pragma unroll
    for (int i = 0; i < 4; ++i) {
        int rr = wm * 64 + i * 16 + frow;
        #pragma unroll
        for (int j = 0; j < 4; ++j) {
            int c = wn * 32 + j * 8 + fcol;
            if (!edge) {
                *(float2*)&out[(size_t)(m0 + rr) * NN + n0 + c] =
                    make_float2(acc[i][j][0], acc[i][j][1]);
                *(float2*)&out[(size_t)(m0 + rr + 8) * NN + n0 + c] =
                    make_float2(acc[i][j][2], acc[i][j][3]);
            } else {
                int m1 = m0 + rr, m2 = m0 + rr + 8, n = n0 + c;
                if (m1 < NN) {
                    if (n < NN)     out[(size_t)m1 * NN + n]     = acc[i][j][0];
                    if (n + 1 < NN) out[(size_t)m1 * NN + n + 1] = acc[i][j][1];
                }
                if (m2 < NN) {
                    if (n < NN)     out[(size_t)m2 * NN + n]     = acc[i][j][2];
                    if (n + 1 < NN) out[(size_t)m2 * NN + n + 1] = acc[i][j][3];
                }
            }
        }
    }

    // mirror store C[n][m] directly from fragments (off-diagonal only)
    if (!diag) {
        bool nedge = (n0 + 127 >= NN);   // m side always interior (bym <= 77)
        #pragma unroll
        for (int i = 0; i < 4; ++i) {
            int rr = wm * 64 + i * 16 + frow;
            size_t m1 = (size_t)(m0 + rr);
            size_t m2 = (size_t)(m0 + rr + 8);
            #pragma unroll
            for (int j = 0; j < 4; ++j) {
                int c = wn * 32 + j * 8 + fcol;
                size_t n1 = (size_t)(n0 + c), n2 = (size_t)(n0 + c + 1);
                if (!nedge) {
                    out[n1 * NN + m1] = acc[i][j][0];
                    out[n2 * NN + m1] = acc[i][j][1];
                    out[n1 * NN + m2] = acc[i][j][2];
                    out[n2 * NN + m2] = acc[i][j][3];
                } else {
                    if (n1 < NN) { out[n1 * NN + m1] = acc[i][j][0];
                                   out[n1 * NN + m2] = acc[i][j][2]; }
                    if (n2 < NN) { out[n2 * NN + m1] = acc[i][j][1];
                                   out[n2 * NN + m2] = acc[i][j][3]; }
                }
            }
        }
    }
}

// ============================================================================
extern "C" void kernel_launch(void* const* d_in, const int* in_sizes, int n_in,
                              void* d_out, int out_size) {
    const float* h  = (const float*)d_in[0];
    const float* W  = (const float*)d_in[1];
    const float* b  = (const float*)d_in[2];
    const int*   es = (const int*)d_in[3];
    const int*   ed = (const int*)d_in[4];
    float*       out = (float*)d_out;

    const size_t smem_hw = (size_t)2 * 128 * TS_STRIDE * sizeof(float);
    cudaFuncSetAttribute(gemm_hw_zero_kernel,
                         cudaFuncAttributeMaxDynamicSharedMemorySize, (int)smem_hw);
    cudaFuncSetAttribute(xxt_mma_kernel,
                         cudaFuncAttributeMaxDynamicSharedMemorySize, SMEM_XXT_BYTES);

    gemm_hw_zero_kernel<<<HW_BLOCKS + ZERO_BLOCKS, 512, smem_hw>>>(h, W);
    csr_count_kernel<<<(NE + 255) / 256, 256>>>(ed);
    csr_scan_kernel<<<1, 1024>>>();
    csr_fill_kernel<<<(NE + 255) / 256, 256>>>(es, ed);
    gather_fuse_kernel<<<NPAD, 128>>>(b);
    xxt_mma_kernel<<<3160, 256, SMEM_XXT_BYTES>>>(out);
}

// round 11
// speedup vs baseline: 1.5032x; 1.0333x over previous
#include <cuda_runtime.h>
#include <cuda_fp16.h>
#include <cstdint>
#include <math.h>

#define NN 10000
#define NE 320000
#define NH 128
#define NPAD 10112            // 79 * 128
#define TS_STRIDE 129
#define XT_STRIDE 136         // f16 tile stride: 272B/row == 16 mod 128 -> conflict-free
#define RS (XT_STRIDE * 2)

// ---------------- scratch ----------------------------------------------------
// INVARIANT: g_deg is all-zero at the start of every kernel_launch call
// (BSS-zero at load; count increments it, fill decrements it back to zero).
__device__ float g_hw[(size_t)NN * NH];
__device__ __half g_y[(size_t)NPAD * NH];    // fp16(x), zero-padded
__device__ int g_deg[NN];
__device__ int g_off[NN + 1];
__device__ int g_csr[NE];

// ============================================================================
// hw = h @ W (blocks [0,79), 512 thr) + CONCURRENT edge-degree count
// (blocks [79,119)); count is legal concurrently because g_deg starts zero
// and nothing in this launch reads it.
#define HW_BLOCKS 79
#define CNT_BLOCKS 40
#define NE4 (NE / 4)                         // 80000 int4 chunks
extern "C" __global__ void __launch_bounds__(512)
gemm_hw_count_kernel(const float* __restrict__ h, const float* __restrict__ W,
                     const int* __restrict__ ed) {
    if (blockIdx.x >= HW_BLOCKS) {
        int gtid = (blockIdx.x - HW_BLOCKS) * 512 + threadIdx.x;  // < 20480
        const int4* ed4 = (const int4*)ed;
        for (int c = gtid; c < NE4; c += CNT_BLOCKS * 512) {
            int4 d4 = ed4[c];
            atomicAdd(&g_deg[d4.x], 1);
            atomicAdd(&g_deg[d4.y], 1);
            atomicAdd(&g_deg[d4.z], 1);
            atomicAdd(&g_deg[d4.w], 1);
        }
        return;
    }
    extern __shared__ float smemf[];
    float* As = smemf;                        // [k][m] 128 x 129
    float* Bs = smemf + 128 * TS_STRIDE;      // [k][n] 128 x 129
    int row0 = blockIdx.x * 128;
    {   // load h tile transposed: 16 warps x 8 rows
        int lane = threadIdx.x & 31, w = threadIdx.x >> 5;
        #pragma unroll
        for (int rr = 0; rr < 8; ++rr) {
            int r = w * 8 + rr;
            bool ok = (row0 + r < NN);
            const float* p = h + (size_t)(row0 + r) * NH;
            #pragma unroll
            for (int q = 0; q < 4; ++q) {
                int k = lane + 32 * q;
                As[k * TS_STRIDE + r] = ok ? p[k] : 0.0f;
            }
        }
        #pragma unroll
        for (int rr = 0; rr < 8; ++rr) {
            int k = w * 8 + rr;
            #pragma unroll
            for (int q = 0; q < 4; ++q) {
                int n = lane + 32 * q;
                Bs[k * TS_STRIDE + n] = W[k * NH + n];
            }
        }
    }
    __syncthreads();
    int tx = threadIdx.x & 15;       // col group: n = tx + 16j, j<8
    int ty = threadIdx.x >> 4;       // row group: m = ty + 32i, i<4
    float acc[4][8] = {};
    #pragma unroll 8
    for (int k = 0; k < 128; ++k) {
        float a[4], b[8];
        #pragma unroll
        for (int i = 0; i < 4; ++i) a[i] = As[k * TS_STRIDE + ty + 32 * i];
        #pragma unroll
        for (int j = 0; j < 8; ++j) b[j] = Bs[k * TS_STRIDE + tx + 16 * j];
        #pragma unroll
        for (int i = 0; i < 4; ++i)
            #pragma unroll
            for (int j = 0; j < 8; ++j)
                acc[i][j] = fmaf(a[i], b[j], acc[i][j]);
    }
    #pragma unroll
    for (int i = 0; i < 4; ++i) {
        int m = row0 + ty + 32 * i;
        if (m < NN)
            #pragma unroll
            for (int j = 0; j < 8; ++j)
                g_hw[(size_t)m * NH + tx + 16 * j] = acc[i][j];
    }
}

// ============================================================================
// exclusive prefix sum of degrees -> g_off (single block; does NOT modify g_deg)
__global__ void csr_scan_kernel() {
    __shared__ int part[1024];
    int tid = threadIdx.x;
    int base = tid * 10;
    int s = 0;
    #pragma unroll
    for (int q = 0; q < 10; ++q) { int i = base + q; if (i < NN) s += g_deg[i]; }
    part[tid] = s;
    __syncthreads();
    #pragma unroll
    for (int off = 1; off < 1024; off <<= 1) {
        int v = (tid >= off) ? part[tid - off] : 0;
        __syncthreads();
        part[tid] += v;
        __syncthreads();
    }
    int run = (tid == 0) ? 0 : part[tid - 1];
    #pragma unroll
    for (int q = 0; q < 10; ++q) {
        int i = base + q;
        if (i < NN) { g_off[i] = run; run += g_deg[i]; }
    }
    if (tid == 0) g_off[NN] = part[1023];
}

// ============================================================================
// fill CSR slots; atomicSub drains g_deg back to zero (self-reset invariant)
__global__ void csr_fill_kernel(const int* __restrict__ es,
                                const int* __restrict__ ed) {
    int i = blockIdx.x * 256 + threadIdx.x;    // < NE4
    if (i < NE4) {
        int4 s4 = ((const int4*)es)[i];
        int4 d4 = ((const int4*)ed)[i];
        int o0 = atomicSub(&g_deg[d4.x], 1);
        int o1 = atomicSub(&g_deg[d4.y], 1);
        int o2 = atomicSub(&g_deg[d4.z], 1);
        int o3 = atomicSub(&g_deg[d4.w], 1);
        g_csr[g_off[d4.x] + o0 - 1] = s4.x;
        g_csr[g_off[d4.y] + o1 - 1] = s4.y;
        g_csr[g_off[d4.z] + o2 - 1] = s4.z;
        g_csr[g_off[d4.w] + o3 - 1] = s4.w;
    }
}

// ============================================================================
// fused gather + bias + relu + fp16 quantize (one block per row)
extern "C" __global__ void gather_fuse_kernel(const float* __restrict__ b) {
    int node = blockIdx.x;
    int c = threadIdx.x;
    size_t o = (size_t)node * NH + c;
    if (node >= NN) { g_y[o] = __float2half(0.0f); return; }
    int beg = g_off[node];
    int end = g_off[node + 1];
    float acc = 0.0f;
    int e = beg;
    for (; e + 4 <= end; e += 4) {
        int s0 = g_csr[e], s1 = g_csr[e + 1], s2 = g_csr[e + 2], s3 = g_csr[e + 3];
        float v0 = g_hw[(size_t)s0 * NH + c];
        float v1 = g_hw[(size_t)s1 * NH + c];
        float v2 = g_hw[(size_t)s2 * NH + c];
        float v3 = g_hw[(size_t)s3 * NH + c];
        acc += (v0 + v1) + (v2 + v3);
    }
    for (; e < end; ++e)
        acc += g_hw[(size_t)g_csr[e] * NH + c];
    float v = acc + b[c];
    v = v > 0.0f ? v : 0.0f;
    g_y[o] = __float2half_rn(v);
}

// ============================================================================
// xxt = y @ y^T — UNCHANGED from R10 (protected win)
#define TILE_BYTES (128 * RS)                 // 34816
#define SMEM_XXT_BYTES (2 * TILE_BYTES)       // 69632 -> occ 2

__device__ __forceinline__ uint32_t smem_u32_of(const void* p) {
    uint32_t a;
    asm("{ .reg .u64 t; cvta.to.shared.u64 t, %1; cvt.u32.u64 %0, t; }"
        : "=r"(a) : "l"(p));
    return a;
}
__device__ __forceinline__ void ldsm_x4(uint32_t r[4], uint32_t addr) {
    asm volatile("ldmatrix.sync.aligned.m8n8.x4.shared.b16 {%0,%1,%2,%3}, [%4];"
                 : "=r"(r[0]), "=r"(r[1]), "=r"(r[2]), "=r"(r[3]) : "r"(addr));
}
__device__ __forceinline__ void cp16(uint32_t dst, const void* src) {
    asm volatile("cp.async.cg.shared.global [%0], [%1], 16;" :: "r"(dst), "l"(src));
}
#define CP_COMMIT() asm volatile("cp.async.commit_group;" ::: "memory")
#define CP_WAIT()   asm volatile("cp.async.wait_all;" ::: "memory")

__device__ __forceinline__ void load_tile_async(const __half* __restrict__ src,
                                                int row0, uint32_t dst) {
    int tid = threadIdx.x;  // 256 threads, 8 x 16B each
    #pragma unroll
    for (int it = 0; it < 8; ++it) {
        int chunk = it * 256 + tid;
        int row = chunk >> 4, c16 = chunk & 15;
        cp16(dst + row * RS + c16 * 16,
             src + (size_t)(row0 + row) * NH + c16 * 8);
    }
}
__device__ __forceinline__ void mma_f32acc(float d[4], const uint32_t a[4],
                                           uint32_t b0, uint32_t b1) {
    asm volatile(
        "mma.sync.aligned.m16n8k16.row.col.f32.f16.f16.f32 "
        "{%0,%1,%2,%3}, {%4,%5,%6,%7}, {%8,%9}, {%0,%1,%2,%3};"
        : "+f"(d[0]), "+f"(d[1]), "+f"(d[2]), "+f"(d[3])
        : "r"(a[0]), "r"(a[1]), "r"(a[2]), "r"(a[3]), "r"(b0), "r"(b1));
}

extern "C" __global__ void __launch_bounds__(256, 2)
xxt_mma_kernel(float* __restrict__ out) {
    // triangular decode: t -> (bym, bxn), bym <= bxn, 79x79 upper triangle
    int t = blockIdx.x;
    int r = (int)((159.0f - sqrtf(25281.0f - 8.0f * (float)t)) * 0.5f);
    if (r < 0) r = 0; if (r > 78) r = 78;
    while ((r + 1) * 79 - ((r + 1) * r) / 2 <= t) ++r;
    while (r * 79 - (r * (r - 1)) / 2 > t) --r;
    int bym = r;
    int bxn = r + (t - (r * 79 - (r * (r - 1)) / 2));
    bool diag = (bxn == bym);

    extern __shared__ char smem[];
    uint32_t uA = smem_u32_of(smem);
    uint32_t uB = uA + TILE_BYTES;

    load_tile_async(g_y, bym * 128, uA);
    if (!diag) load_tile_async(g_y, bxn * 128, uB);
    else       uB = uA;
    CP_COMMIT(); CP_WAIT();
    __syncthreads();

    int tid = threadIdx.x, lane = tid & 31, wid = tid >> 5;
    int wm = wid & 1;
    int wn = wid >> 1;
    int frow = lane >> 2;
    int fcol = 2 * (lane & 3);
    uint32_t laneA = (uint32_t)((lane & 15) * RS + (lane >> 4) * 16);
    uint32_t laneB = (uint32_t)((((lane >> 4) & 1) * 8 + (lane & 7)) * RS
                                + ((lane >> 3) & 1) * 16);

    float acc[4][4][4] = {};

    #pragma unroll
    for (int k0 = 0; k0 < 8; ++k0) {
        uint32_t kb = k0 * 32;
        uint32_t bf[2][4];
        #pragma unroll
        for (int jp = 0; jp < 2; ++jp)
            ldsm_x4(bf[jp], uB + laneB + (uint32_t)((wn * 32 + jp * 16) * RS) + kb);
        #pragma unroll
        for (int i = 0; i < 4; ++i) {
            uint32_t a[4];
            ldsm_x4(a, uA + laneA + (uint32_t)((wm * 64 + i * 16) * RS) + kb);
            #pragma unroll
            for (int jp = 0; jp < 2; ++jp) {
                mma_f32acc(acc[i][2 * jp],     a, bf[jp][0], bf[jp][1]);
                mma_f32acc(acc[i][2 * jp + 1], a, bf[jp][2], bf[jp][3]);
            }
        }
    }

    int m0 = bym * 128, n0 = bxn * 128;
    bool edge = (n0 + 127 >= NN) || (m0 + 127 >= NN);

    // main-tile store C[m][n] (float2, default policy — L2 write-combines)
    #pragma unroll
    for (int i = 0; i < 4; ++i) {
        int rr = wm * 64 + i * 16 + frow;
        #pragma unroll
        for (int j = 0; j < 4; ++j) {
            int c = wn * 32 + j * 8 + fcol;
            if (!edge) {
                *(float2*)&out[(size_t)(m0 + rr) * NN + n0 + c] =
                    make_float2(acc[i][j][0], acc[i][j][1]);
                *(float2*)&out[(size_t)(m0 + rr + 8) * NN + n0 + c] =
                    make_float2(acc[i][j][2], acc[i][j][3]);
            } else {
                int m1 = m0 + rr, m2 = m0 + rr + 8, n = n0 + c;
                if (m1 < NN) {
                    if (n < NN)     out[(size_t)m1 * NN + n]     = acc[i][j][0];
                    if (n + 1 < NN) out[(size_t)m1 * NN + n + 1] = acc[i][j][1];
                }
                if (m2 < NN) {
                    if (n < NN)     out[(size_t)m2 * NN + n]     = acc[i][j][2];
                    if (n + 1 < NN) out[(size_t)m2 * NN + n + 1] = acc[i][j][3];
                }
            }
        }
    }

    // mirror store C[n][m] directly from fragments (off-diagonal only)
    if (!diag) {
        bool nedge = (n0 + 127 >= NN);   // m side always interior (bym <= 77)
        #pragma unroll
        for (int i = 0; i < 4; ++i) {
            int rr = wm * 64 + i * 16 + frow;
            size_t m1 = (size_t)(m0 + rr);
            size_t m2 = (size_t)(m0 + rr + 8);
            #pragma unroll
            for (int j = 0; j < 4; ++j) {
                int c = wn * 32 + j * 8 + fcol;
                size_t n1 = (size_t)(n0 + c), n2 = (size_t)(n0 + c + 1);
                if (!nedge) {
                    out[n1 * NN + m1] = acc[i][j][0];
                    out[n2 * NN + m1] = acc[i][j][1];
                    out[n1 * NN + m2] = acc[i][j][2];
                    out[n2 * NN + m2] = acc[i][j][3];
                } else {
                    if (n1 < NN) { out[n1 * NN + m1] = acc[i][j][0];
                                   out[n1 * NN + m2] = acc[i][j][2]; }
                    if (n2 < NN) { out[n2 * NN + m1] = acc[i][j][1];
                                   out[n2 * NN + m2] = acc[i][j][3]; }
                }
            }
        }
    }
}

// ============================================================================
extern "C" void kernel_launch(void* const* d_in, const int* in_sizes, int n_in,
                              void* d_out, int out_size) {
    const float* h  = (const float*)d_in[0];
    const float* W  = (const float*)d_in[1];
    const float* b  = (const float*)d_in[2];
    const int*   es = (const int*)d_in[3];
    const int*   ed = (const int*)d_in[4];
    float*       out = (float*)d_out;

    const size_t smem_hw = (size_t)2 * 128 * TS_STRIDE * sizeof(float);
    cudaFuncSetAttribute(gemm_hw_count_kernel,
                         cudaFuncAttributeMaxDynamicSharedMemorySize, (int)smem_hw);
    cudaFuncSetAttribute(xxt_mma_kernel,
                         cudaFuncAttributeMaxDynamicSharedMemorySize, SMEM_XXT_BYTES);

    // hw = h@W (blocks 0..78) and edge-degree count (blocks 79..118), one launch
    gemm_hw_count_kernel<<<HW_BLOCKS + CNT_BLOCKS, 512, smem_hw>>>(h, W, ed);
    csr_scan_kernel<<<1, 1024>>>();
    csr_fill_kernel<<<(NE4 + 255) / 256, 256>>>(es, ed);
    gather_fuse_kernel<<<NPAD, 128>>>(b);
    xxt_mma_kernel<<<3160, 256, SMEM_XXT_BYTES>>>(out);
}

// round 12
// speedup vs baseline: 1.5845x; 1.0541x over previous
#include <cuda_runtime.h>
#include <cuda_fp16.h>
#include <cstdint>
#include <math.h>

#define NN 10000
#define NE 320000
#define NH 128
#define NPAD 10112            // 79 * 128
#define TS_STRIDE 129
#define XT_STRIDE 136         // f16 tile stride: 272B/row == 16 mod 128 -> conflict-free
#define RS (XT_STRIDE * 2)

// ---------------- scratch ----------------------------------------------------
// INVARIANT: g_deg is all-zero at the start of every kernel_launch call
// (BSS-zero at load; count increments it, fill decrements it back to zero).
__device__ float g_hw[(size_t)NN * NH];
__device__ __half g_y[(size_t)NPAD * NH];    // fp16(x), zero-padded
__device__ int g_deg[NN];
__device__ int g_off[NN + 1];
__device__ int g_csr[NE];

// ============================================================================
// hw = h @ W (blocks [0,79), 512 thr) + CONCURRENT edge-degree count
#define HW_BLOCKS 79
#define CNT_BLOCKS 40
#define NE4 (NE / 4)                         // 80000 int4 chunks
extern "C" __global__ void __launch_bounds__(512)
gemm_hw_count_kernel(const float* __restrict__ h, const float* __restrict__ W,
                     const int* __restrict__ ed) {
    if (blockIdx.x >= HW_BLOCKS) {
        int gtid = (blockIdx.x - HW_BLOCKS) * 512 + threadIdx.x;  // < 20480
        const int4* ed4 = (const int4*)ed;
        for (int c = gtid; c < NE4; c += CNT_BLOCKS * 512) {
            int4 d4 = ed4[c];
            atomicAdd(&g_deg[d4.x], 1);
            atomicAdd(&g_deg[d4.y], 1);
            atomicAdd(&g_deg[d4.z], 1);
            atomicAdd(&g_deg[d4.w], 1);
        }
        return;
    }
    extern __shared__ float smemf[];
    float* As = smemf;                        // [k][m] 128 x 129
    float* Bs = smemf + 128 * TS_STRIDE;      // [k][n] 128 x 129
    int row0 = blockIdx.x * 128;
    {   // load h tile transposed: 16 warps x 8 rows
        int lane = threadIdx.x & 31, w = threadIdx.x >> 5;
        #pragma unroll
        for (int rr = 0; rr < 8; ++rr) {
            int r = w * 8 + rr;
            bool ok = (row0 + r < NN);
            const float* p = h + (size_t)(row0 + r) * NH;
            #pragma unroll
            for (int q = 0; q < 4; ++q) {
                int k = lane + 32 * q;
                As[k * TS_STRIDE + r] = ok ? p[k] : 0.0f;
            }
        }
        #pragma unroll
        for (int rr = 0; rr < 8; ++rr) {
            int k = w * 8 + rr;
            #pragma unroll
            for (int q = 0; q < 4; ++q) {
                int n = lane + 32 * q;
                Bs[k * TS_STRIDE + n] = W[k * NH + n];
            }
        }
    }
    __syncthreads();
    int tx = threadIdx.x & 15;
    int ty = threadIdx.x >> 4;
    float acc[4][8] = {};
    #pragma unroll 8
    for (int k = 0; k < 128; ++k) {
        float a[4], b[8];
        #pragma unroll
        for (int i = 0; i < 4; ++i) a[i] = As[k * TS_STRIDE + ty + 32 * i];
        #pragma unroll
        for (int j = 0; j < 8; ++j) b[j] = Bs[k * TS_STRIDE + tx + 16 * j];
        #pragma unroll
        for (int i = 0; i < 4; ++i)
            #pragma unroll
            for (int j = 0; j < 8; ++j)
                acc[i][j] = fmaf(a[i], b[j], acc[i][j]);
    }
    #pragma unroll
    for (int i = 0; i < 4; ++i) {
        int m = row0 + ty + 32 * i;
        if (m < NN)
            #pragma unroll
            for (int j = 0; j < 8; ++j)
                g_hw[(size_t)m * NH + tx + 16 * j] = acc[i][j];
    }
}

// ============================================================================
// exclusive prefix sum of degrees -> g_off (does NOT modify g_deg)
__global__ void csr_scan_kernel() {
    __shared__ int part[1024];
    int tid = threadIdx.x;
    int base = tid * 10;
    int s = 0;
    #pragma unroll
    for (int q = 0; q < 10; ++q) { int i = base + q; if (i < NN) s += g_deg[i]; }
    part[tid] = s;
    __syncthreads();
    #pragma unroll
    for (int off = 1; off < 1024; off <<= 1) {
        int v = (tid >= off) ? part[tid - off] : 0;
        __syncthreads();
        part[tid] += v;
        __syncthreads();
    }
    int run = (tid == 0) ? 0 : part[tid - 1];
    #pragma unroll
    for (int q = 0; q < 10; ++q) {
        int i = base + q;
        if (i < NN) { g_off[i] = run; run += g_deg[i]; }
    }
    if (tid == 0) g_off[NN] = part[1023];
}

// ============================================================================
// fill CSR slots; atomicSub drains g_deg back to zero (self-reset invariant)
__global__ void csr_fill_kernel(const int* __restrict__ es,
                                const int* __restrict__ ed) {
    int i = blockIdx.x * 256 + threadIdx.x;    // < NE4
    if (i < NE4) {
        int4 s4 = ((const int4*)es)[i];
        int4 d4 = ((const int4*)ed)[i];
        int o0 = atomicSub(&g_deg[d4.x], 1);
        int o1 = atomicSub(&g_deg[d4.y], 1);
        int o2 = atomicSub(&g_deg[d4.z], 1);
        int o3 = atomicSub(&g_deg[d4.w], 1);
        g_csr[g_off[d4.x] + o0 - 1] = s4.x;
        g_csr[g_off[d4.y] + o1 - 1] = s4.y;
        g_csr[g_off[d4.z] + o2 - 1] = s4.z;
        g_csr[g_off[d4.w] + o3 - 1] = s4.w;
    }
}

// ============================================================================
// gather + bias + relu + fp16 quantize — float4 path, 4 edges in flight.
// Warp q handles edges beg+q, beg+q+4, ...; lane owns channels 4*lane..+3.
extern "C" __global__ void __launch_bounds__(128)
gather_fuse_kernel(const float* __restrict__ b) {
    __shared__ float sred[4 * NH];           // 4 warps x 128 channels
    int node = blockIdx.x;
    int tid = threadIdx.x;
    int quad = tid >> 5, lane = tid & 31;
    int c4 = lane << 2;

    if (node >= NN) {
        if (tid < NH) g_y[(size_t)node * NH + tid] = __float2half(0.0f);
        return;
    }
    int beg = g_off[node];
    int end = g_off[node + 1];

    float4 a4 = make_float4(0.f, 0.f, 0.f, 0.f);
    int e = beg + quad;
    // 2-deep software pipeline for MLP
    for (; e + 4 < end; e += 8) {
        int s0 = g_csr[e];
        int s1 = g_csr[e + 4];
        float4 v0 = *(const float4*)&g_hw[(size_t)s0 * NH + c4];
        float4 v1 = *(const float4*)&g_hw[(size_t)s1 * NH + c4];
        a4.x += v0.x + v1.x;
        a4.y += v0.y + v1.y;
        a4.z += v0.z + v1.z;
        a4.w += v0.w + v1.w;
    }
    if (e < end) {
        int s0 = g_csr[e];
        float4 v0 = *(const float4*)&g_hw[(size_t)s0 * NH + c4];
        a4.x += v0.x; a4.y += v0.y; a4.z += v0.z; a4.w += v0.w;
    }
    *(float4*)&sred[quad * NH + c4] = a4;
    __syncthreads();

    int c = tid;   // 0..127: one channel per thread
    float v = sred[c] + sred[NH + c] + sred[2 * NH + c] + sred[3 * NH + c];
    v += b[c];
    v = v > 0.0f ? v : 0.0f;
    g_y[(size_t)node * NH + c] = __float2half_rn(v);
}

// ============================================================================
// xxt = y @ y^T — UNCHANGED from R10/R11 (protected win)
#define TILE_BYTES (128 * RS)                 // 34816
#define SMEM_XXT_BYTES (2 * TILE_BYTES)       // 69632 -> occ 2

__device__ __forceinline__ uint32_t smem_u32_of(const void* p) {
    uint32_t a;
    asm("{ .reg .u64 t; cvta.to.shared.u64 t, %1; cvt.u32.u64 %0, t; }"
        : "=r"(a) : "l"(p));
    return a;
}
__device__ __forceinline__ void ldsm_x4(uint32_t r[4], uint32_t addr) {
    asm volatile("ldmatrix.sync.aligned.m8n8.x4.shared.b16 {%0,%1,%2,%3}, [%4];"
                 : "=r"(r[0]), "=r"(r[1]), "=r"(r[2]), "=r"(r[3]) : "r"(addr));
}
__device__ __forceinline__ void cp16(uint32_t dst, const void* src) {
    asm volatile("cp.async.cg.shared.global [%0], [%1], 16;" :: "r"(dst), "l"(src));
}
#define CP_COMMIT() asm volatile("cp.async.commit_group;" ::: "memory")
#define CP_WAIT()   asm volatile("cp.async.wait_all;" ::: "memory")

__device__ __forceinline__ void load_tile_async(const __half* __restrict__ src,
                                                int row0, uint32_t dst) {
    int tid = threadIdx.x;  // 256 threads, 8 x 16B each
    #pragma unroll
    for (int it = 0; it < 8; ++it) {
        int chunk = it * 256 + tid;
        int row = chunk >> 4, c16 = chunk & 15;
        cp16(dst + row * RS + c16 * 16,
             src + (size_t)(row0 + row) * NH + c16 * 8);
    }
}
__device__ __forceinline__ void mma_f32acc(float d[4], const uint32_t a[4],
                                           uint32_t b0, uint32_t b1) {
    asm volatile(
        "mma.sync.aligned.m16n8k16.row.col.f32.f16.f16.f32 "
        "{%0,%1,%2,%3}, {%4,%5,%6,%7}, {%8,%9}, {%0,%1,%2,%3};"
        : "+f"(d[0]), "+f"(d[1]), "+f"(d[2]), "+f"(d[3])
        : "r"(a[0]), "r"(a[1]), "r"(a[2]), "r"(a[3]), "r"(b0), "r"(b1));
}

extern "C" __global__ void __launch_bounds__(256, 2)
xxt_mma_kernel(float* __restrict__ out) {
    // triangular decode: t -> (bym, bxn), bym <= bxn, 79x79 upper triangle
    int t = blockIdx.x;
    int r = (int)((159.0f - sqrtf(25281.0f - 8.0f * (float)t)) * 0.5f);
    if (r < 0) r = 0; if (r > 78) r = 78;
    while ((r + 1) * 79 - ((r + 1) * r) / 2 <= t) ++r;
    while (r * 79 - (r * (r - 1)) / 2 > t) --r;
    int bym = r;
    int bxn = r + (t - (r * 79 - (r * (r - 1)) / 2));
    bool diag = (bxn == bym);

    extern __shared__ char smem[];
    uint32_t uA = smem_u32_of(smem);
    uint32_t uB = uA + TILE_BYTES;

    load_tile_async(g_y, bym * 128, uA);
    if (!diag) load_tile_async(g_y, bxn * 128, uB);
    else       uB = uA;
    CP_COMMIT(); CP_WAIT();
    __syncthreads();

    int tid = threadIdx.x, lane = tid & 31, wid = tid >> 5;
    int wm = wid & 1;
    int wn = wid >> 1;
    int frow = lane >> 2;
    int fcol = 2 * (lane & 3);
    uint32_t laneA = (uint32_t)((lane & 15) * RS + (lane >> 4) * 16);
    uint32_t laneB = (uint32_t)((((lane >> 4) & 1) * 8 + (lane & 7)) * RS
                                + ((lane >> 3) & 1) * 16);

    float acc[4][4][4] = {};

    #pragma unroll
    for (int k0 = 0; k0 < 8; ++k0) {
        uint32_t kb = k0 * 32;
        uint32_t bf[2][4];
        #pragma unroll
        for (int jp = 0; jp < 2; ++jp)
            ldsm_x4(bf[jp], uB + laneB + (uint32_t)((wn * 32 + jp * 16) * RS) + kb);
        #pragma unroll
        for (int i = 0; i < 4; ++i) {
            uint32_t a[4];
            ldsm_x4(a, uA + laneA + (uint32_t)((wm * 64 + i * 16) * RS) + kb);
            #pragma unroll
            for (int jp = 0; jp < 2; ++jp) {
                mma_f32acc(acc[i][2 * jp],     a, bf[jp][0], bf[jp][1]);
                mma_f32acc(acc[i][2 * jp + 1], a, bf[jp][2], bf[jp][3]);
            }
        }
    }

    int m0 = bym * 128, n0 = bxn * 128;
    bool edge = (n0 + 127 >= NN) || (m0 + 127 >= NN);

    // main-tile store C[m][n] (float2, default policy — L2 write-combines)
    #pragma unroll
    for (int i = 0; i < 4; ++i) {
        int rr = wm * 64 + i * 16 + frow;
        #pragma unroll
        for (int j = 0; j < 4; ++j) {
            int c = wn * 32 + j * 8 + fcol;
            if (!edge) {
                *(float2*)&out[(size_t)(m0 + rr) * NN + n0 + c] =
                    make_float2(acc[i][j][0], acc[i][j][1]);
                *(float2*)&out[(size_t)(m0 + rr + 8) * NN + n0 + c] =
                    make_float2(acc[i][j][2], acc[i][j][3]);
            } else {
                int m1 = m0 + rr, m2 = m0 + rr + 8, n = n0 + c;
                if (m1 < NN) {
                    if (n < NN)     out[(size_t)m1 * NN + n]     = acc[i][j][0];
                    if (n + 1 < NN) out[(size_t)m1 * NN + n + 1] = acc[i][j][1];
                }
                if (m2 < NN) {
                    if (n < NN)     out[(size_t)m2 * NN + n]     = acc[i][j][2];
                    if (n + 1 < NN) out[(size_t)m2 * NN + n + 1] = acc[i][j][3];
                }
            }
        }
    }

    // mirror store C[n][m] directly from fragments (off-diagonal only)
    if (!diag) {
        bool nedge = (n0 + 127 >= NN);   // m side always interior (bym <= 77)
        #pragma unroll
        for (int i = 0; i < 4; ++i) {
            int rr = wm * 64 + i * 16 + frow;
            size_t m1 = (size_t)(m0 + rr);
            size_t m2 = (size_t)(m0 + rr + 8);
            #pragma unroll
            for (int j = 0; j < 4; ++j) {
                int c = wn * 32 + j * 8 + fcol;
                size_t n1 = (size_t)(n0 + c), n2 = (size_t)(n0 + c + 1);
                if (!nedge) {
                    out[n1 * NN + m1] = acc[i][j][0];
                    out[n2 * NN + m1] = acc[i][j][1];
                    out[n1 * NN + m2] = acc[i][j][2];
                    out[n2 * NN + m2] = acc[i][j][3];
                } else {
                    if (n1 < NN) { out[n1 * NN + m1] = acc[i][j][0];
                                   out[n1 * NN + m2] = acc[i][j][2]; }
                    if (n2 < NN) { out[n2 * NN + m1] = acc[i][j][1];
                                   out[n2 * NN + m2] = acc[i][j][3]; }
                }
            }
        }
    }
}

// ============================================================================
extern "C" void kernel_launch(void* const* d_in, const int* in_sizes, int n_in,
                              void* d_out, int out_size) {
    const float* h  = (const float*)d_in[0];
    const float* W  = (const float*)d_in[1];
    const float* b  = (const float*)d_in[2];
    const int*   es = (const int*)d_in[3];
    const int*   ed = (const int*)d_in[4];
    float*       out = (float*)d_out;

    const size_t smem_hw = (size_t)2 * 128 * TS_STRIDE * sizeof(float);
    cudaFuncSetAttribute(gemm_hw_count_kernel,
                         cudaFuncAttributeMaxDynamicSharedMemorySize, (int)smem_hw);
    cudaFuncSetAttribute(xxt_mma_kernel,
                         cudaFuncAttributeMaxDynamicSharedMemorySize, SMEM_XXT_BYTES);

    gemm_hw_count_kernel<<<HW_BLOCKS + CNT_BLOCKS, 512, smem_hw>>>(h, W, ed);
    csr_scan_kernel<<<1, 1024>>>();
    csr_fill_kernel<<<(NE4 + 255) / 256, 256>>>(es, ed);
    gather_fuse_kernel<<<NPAD, 128>>>(b);
    xxt_mma_kernel<<<3160, 256, SMEM_XXT_BYTES>>>(out);
}

// round 13
// speedup vs baseline: 1.5874x; 1.0018x over previous
#include <cuda_runtime.h>
#include <cuda_fp16.h>
#include <cstdint>
#include <math.h>

#define NN 10000
#define NE 320000
#define NH 128
#define NPAD 10112            // 79 * 128
#define TS_STRIDE 129
#define XT_STRIDE 136         // f16 tile stride: 272B/row == 16 mod 128 -> conflict-free
#define RS (XT_STRIDE * 2)

// ---------------- scratch ----------------------------------------------------
// INVARIANT: g_deg is all-zero at the start of every kernel_launch call
// (BSS-zero at load; count increments it, fill decrements it back to zero).
__device__ __half g_hw[(size_t)NN * NH];     // fp16 hw = h@W (halves gather traffic)
__device__ __half g_y[(size_t)NPAD * NH];    // fp16(x), zero-padded
__device__ int g_deg[NN];
__device__ int g_off[NN + 1];
__device__ int g_csr[NE];

// ============================================================================
// hw = h @ W (blocks [0,79), 512 thr) + CONCURRENT edge-degree count
#define HW_BLOCKS 79
#define CNT_BLOCKS 40
#define NE4 (NE / 4)                         // 80000 int4 chunks
extern "C" __global__ void __launch_bounds__(512)
gemm_hw_count_kernel(const float* __restrict__ h, const float* __restrict__ W,
                     const int* __restrict__ ed) {
    if (blockIdx.x >= HW_BLOCKS) {
        int gtid = (blockIdx.x - HW_BLOCKS) * 512 + threadIdx.x;  // < 20480
        const int4* ed4 = (const int4*)ed;
        for (int c = gtid; c < NE4; c += CNT_BLOCKS * 512) {
            int4 d4 = ed4[c];
            atomicAdd(&g_deg[d4.x], 1);
            atomicAdd(&g_deg[d4.y], 1);
            atomicAdd(&g_deg[d4.z], 1);
            atomicAdd(&g_deg[d4.w], 1);
        }
        return;
    }
    extern __shared__ float smemf[];
    float* As = smemf;                        // [k][m] 128 x 129
    float* Bs = smemf + 128 * TS_STRIDE;      // [k][n] 128 x 129
    int row0 = blockIdx.x * 128;
    {   // load h tile transposed: 16 warps x 8 rows
        int lane = threadIdx.x & 31, w = threadIdx.x >> 5;
        #pragma unroll
        for (int rr = 0; rr < 8; ++rr) {
            int r = w * 8 + rr;
            bool ok = (row0 + r < NN);
            const float* p = h + (size_t)(row0 + r) * NH;
            #pragma unroll
            for (int q = 0; q < 4; ++q) {
                int k = lane + 32 * q;
                As[k * TS_STRIDE + r] = ok ? p[k] : 0.0f;
            }
        }
        #pragma unroll
        for (int rr = 0; rr < 8; ++rr) {
            int k = w * 8 + rr;
            #pragma unroll
            for (int q = 0; q < 4; ++q) {
                int n = lane + 32 * q;
                Bs[k * TS_STRIDE + n] = W[k * NH + n];
            }
        }
    }
    __syncthreads();
    // thread owns rows m = ty + 32i (i<4), col pairs n = 2*tx + 32*j (j<4)
    int tx = threadIdx.x & 15;
    int ty = threadIdx.x >> 4;
    float acc[4][4][2] = {};
    #pragma unroll 8
    for (int k = 0; k < 128; ++k) {
        float a[4], b[4][2];
        #pragma unroll
        for (int i = 0; i < 4; ++i) a[i] = As[k * TS_STRIDE + ty + 32 * i];
        #pragma unroll
        for (int j = 0; j < 4; ++j) {
            b[j][0] = Bs[k * TS_STRIDE + 2 * tx + 32 * j];
            b[j][1] = Bs[k * TS_STRIDE + 2 * tx + 32 * j + 1];
        }
        #pragma unroll
        for (int i = 0; i < 4; ++i)
            #pragma unroll
            for (int j = 0; j < 4; ++j) {
                acc[i][j][0] = fmaf(a[i], b[j][0], acc[i][j][0]);
                acc[i][j][1] = fmaf(a[i], b[j][1], acc[i][j][1]);
            }
    }
    #pragma unroll
    for (int i = 0; i < 4; ++i) {
        int m = row0 + ty + 32 * i;
        if (m < NN)
            #pragma unroll
            for (int j = 0; j < 4; ++j) {
                __half2 hv = __floats2half2_rn(acc[i][j][0], acc[i][j][1]);
                *(__half2*)&g_hw[(size_t)m * NH + 2 * tx + 32 * j] = hv;
            }
    }
}

// ============================================================================
// exclusive prefix sum of degrees -> g_off (does NOT modify g_deg)
__global__ void csr_scan_kernel() {
    __shared__ int part[1024];
    int tid = threadIdx.x;
    int base = tid * 10;
    int s = 0;
    #pragma unroll
    for (int q = 0; q < 10; ++q) { int i = base + q; if (i < NN) s += g_deg[i]; }
    part[tid] = s;
    __syncthreads();
    #pragma unroll
    for (int off = 1; off < 1024; off <<= 1) {
        int v = (tid >= off) ? part[tid - off] : 0;
        __syncthreads();
        part[tid] += v;
        __syncthreads();
    }
    int run = (tid == 0) ? 0 : part[tid - 1];
    #pragma unroll
    for (int q = 0; q < 10; ++q) {
        int i = base + q;
        if (i < NN) { g_off[i] = run; run += g_deg[i]; }
    }
    if (tid == 0) g_off[NN] = part[1023];
}

// ============================================================================
// fill CSR slots; atomicSub drains g_deg back to zero (self-reset invariant)
__global__ void csr_fill_kernel(const int* __restrict__ es,
                                const int* __restrict__ ed) {
    int i = blockIdx.x * 256 + threadIdx.x;    // < NE4
    if (i < NE4) {
        int4 s4 = ((const int4*)es)[i];
        int4 d4 = ((const int4*)ed)[i];
        int o0 = atomicSub(&g_deg[d4.x], 1);
        int o1 = atomicSub(&g_deg[d4.y], 1);
        int o2 = atomicSub(&g_deg[d4.z], 1);
        int o3 = atomicSub(&g_deg[d4.w], 1);
        g_csr[g_off[d4.x] + o0 - 1] = s4.x;
        g_csr[g_off[d4.y] + o1 - 1] = s4.y;
        g_csr[g_off[d4.z] + o2 - 1] = s4.z;
        g_csr[g_off[d4.w] + o3 - 1] = s4.w;
    }
}

// ============================================================================
// gather + bias + relu + fp16 quantize — fp16 rows, 8B per lane per edge.
// Warp q handles edges beg+q, beg+q+4, ...; lane owns channels 4*lane..+3.
extern "C" __global__ void __launch_bounds__(128)
gather_fuse_kernel(const float* __restrict__ b) {
    __shared__ float sred[4 * NH];           // 4 warps x 128 channels
    int node = blockIdx.x;
    int tid = threadIdx.x;
    int quad = tid >> 5, lane = tid & 31;
    int c4 = lane << 2;

    if (node >= NN) {
        if (tid < NH) g_y[(size_t)node * NH + tid] = __float2half(0.0f);
        return;
    }
    int beg = g_off[node];
    int end = g_off[node + 1];

    float4 a4 = make_float4(0.f, 0.f, 0.f, 0.f);
    int e = beg + quad;
    // 2-deep software pipeline for MLP
    for (; e + 4 < end; e += 8) {
        int s0 = g_csr[e];
        int s1 = g_csr[e + 4];
        uint2 u0 = *(const uint2*)&g_hw[(size_t)s0 * NH + c4];
        uint2 u1 = *(const uint2*)&g_hw[(size_t)s1 * NH + c4];
        float2 f00 = __half22float2(*(__half2*)&u0.x);
        float2 f01 = __half22float2(*(__half2*)&u0.y);
        float2 f10 = __half22float2(*(__half2*)&u1.x);
        float2 f11 = __half22float2(*(__half2*)&u1.y);
        a4.x += f00.x + f10.x;
        a4.y += f00.y + f10.y;
        a4.z += f01.x + f11.x;
        a4.w += f01.y + f11.y;
    }
    if (e < end) {
        int s0 = g_csr[e];
        uint2 u0 = *(const uint2*)&g_hw[(size_t)s0 * NH + c4];
        float2 f00 = __half22float2(*(__half2*)&u0.x);
        float2 f01 = __half22float2(*(__half2*)&u0.y);
        a4.x += f00.x; a4.y += f00.y; a4.z += f01.x; a4.w += f01.y;
    }
    *(float4*)&sred[quad * NH + c4] = a4;
    __syncthreads();

    int c = tid;   // 0..127: one channel per thread
    float v = sred[c] + sred[NH + c] + sred[2 * NH + c] + sred[3 * NH + c];
    v += b[c];
    v = v > 0.0f ? v : 0.0f;
    g_y[(size_t)node * NH + c] = __float2half_rn(v);
}

// ============================================================================
// xxt = y @ y^T — UNCHANGED (protected win; at DRAM-write floor)
#define TILE_BYTES (128 * RS)                 // 34816
#define SMEM_XXT_BYTES (2 * TILE_BYTES)       // 69632 -> occ 2

__device__ __forceinline__ uint32_t smem_u32_of(const void* p) {
    uint32_t a;
    asm("{ .reg .u64 t; cvta.to.shared.u64 t, %1; cvt.u32.u64 %0, t; }"
        : "=r"(a) : "l"(p));
    return a;
}
__device__ __forceinline__ void ldsm_x4(uint32_t r[4], uint32_t addr) {
    asm volatile("ldmatrix.sync.aligned.m8n8.x4.shared.b16 {%0,%1,%2,%3}, [%4];"
                 : "=r"(r[0]), "=r"(r[1]), "=r"(r[2]), "=r"(r[3]) : "r"(addr));
}
__device__ __forceinline__ void cp16(uint32_t dst, const void* src) {
    asm volatile("cp.async.cg.shared.global [%0], [%1], 16;" :: "r"(dst), "l"(src));
}
#define CP_COMMIT() asm volatile("cp.async.commit_group;" ::: "memory")
#define CP_WAIT()   asm volatile("cp.async.wait_all;" ::: "memory")

__device__ __forceinline__ void load_tile_async(const __half* __restrict__ src,
                                                int row0, uint32_t dst) {
    int tid = threadIdx.x;  // 256 threads, 8 x 16B each
    #pragma unroll
    for (int it = 0; it < 8; ++it) {
        int chunk = it * 256 + tid;
        int row = chunk >> 4, c16 = chunk & 15;
        cp16(dst + row * RS + c16 * 16,
             src + (size_t)(row0 + row) * NH + c16 * 8);
    }
}
__device__ __forceinline__ void mma_f32acc(float d[4], const uint32_t a[4],
                                           uint32_t b0, uint32_t b1) {
    asm volatile(
        "mma.sync.aligned.m16n8k16.row.col.f32.f16.f16.f32 "
        "{%0,%1,%2,%3}, {%4,%5,%6,%7}, {%8,%9}, {%0,%1,%2,%3};"
        : "+f"(d[0]), "+f"(d[1]), "+f"(d[2]), "+f"(d[3])
        : "r"(a[0]), "r"(a[1]), "r"(a[2]), "r"(a[3]), "r"(b0), "r"(b1));
}

extern "C" __global__ void __launch_bounds__(256, 2)
xxt_mma_kernel(float* __restrict__ out) {
    // triangular decode: t -> (bym, bxn), bym <= bxn, 79x79 upper triangle
    int t = blockIdx.x;
    int r = (int)((159.0f - sqrtf(25281.0f - 8.0f * (float)t)) * 0.5f);
    if (r < 0) r = 0; if (r > 78) r = 78;
    while ((r + 1) * 79 - ((r + 1) * r) / 2 <= t) ++r;
    while (r * 79 - (r * (r - 1)) / 2 > t) --r;
    int bym = r;
    int bxn = r + (t - (r * 79 - (r * (r - 1)) / 2));
    bool diag = (bxn == bym);

    extern __shared__ char smem[];
    uint32_t uA = smem_u32_of(smem);
    uint32_t uB = uA + TILE_BYTES;

    load_tile_async(g_y, bym * 128, uA);
    if (!diag) load_tile_async(g_y, bxn * 128, uB);
    else       uB = uA;
    CP_COMMIT(); CP_WAIT();
    __syncthreads();

    int tid = threadIdx.x, lane = tid & 31, wid = tid >> 5;
    int wm = wid & 1;
    int wn = wid >> 1;
    int frow = lane >> 2;
    int fcol = 2 * (lane & 3);
    uint32_t laneA = (uint32_t)((lane & 15) * RS + (lane >> 4) * 16);
    uint32_t laneB = (uint32_t)((((lane >> 4) & 1) * 8 + (lane & 7)) * RS
                                + ((lane >> 3) & 1) * 16);

    float acc[4][4][4] = {};

    #pragma unroll
    for (int k0 = 0; k0 < 8; ++k0) {
        uint32_t kb = k0 * 32;
        uint32_t bf[2][4];
        #pragma unroll
        for (int jp = 0; jp < 2; ++jp)
            ldsm_x4(bf[jp], uB + laneB + (uint32_t)((wn * 32 + jp * 16) * RS) + kb);
        #pragma unroll
        for (int i = 0; i < 4; ++i) {
            uint32_t a[4];
            ldsm_x4(a, uA + laneA + (uint32_t)((wm * 64 + i * 16) * RS) + kb);
            #pragma unroll
            for (int jp = 0; jp < 2; ++jp) {
                mma_f32acc(acc[i][2 * jp],     a, bf[jp][0], bf[jp][1]);
                mma_f32acc(acc[i][2 * jp + 1], a, bf[jp][2], bf[jp][3]);
            }
        }
    }

    int m0 = bym * 128, n0 = bxn * 128;
    bool edge = (n0 + 127 >= NN) || (m0 + 127 >= NN);

    // main-tile store C[m][n] (float2, default policy — L2 write-combines)
    #pragma unroll
    for (int i = 0; i < 4; ++i) {
        int rr = wm * 64 + i * 16 + frow;
        #pragma unroll
        for (int j = 0; j < 4; ++j) {
            int c = wn * 32 + j * 8 + fcol;
            if (!edge) {
                *(float2*)&out[(size_t)(m0 + rr) * NN + n0 + c] =
                    make_float2(acc[i][j][0], acc[i][j][1]);
                *(float2*)&out[(size_t)(m0 + rr + 8) * NN + n0 + c] =
                    make_float2(acc[i][j][2], acc[i][j][3]);
            } else {
                int m1 = m0 + rr, m2 = m0 + rr + 8, n = n0 + c;
                if (m1 < NN) {
                    if (n < NN)     out[(size_t)m1 * NN + n]     = acc[i][j][0];
                    if (n + 1 < NN) out[(size_t)m1 * NN + n + 1] = acc[i][j][1];
                }
                if (m2 < NN) {
                    if (n < NN)     out[(size_t)m2 * NN + n]     = acc[i][j][2];
                    if (n + 1 < NN) out[(size_t)m2 * NN + n + 1] = acc[i][j][3];
                }
            }
        }
    }

    // mirror store C[n][m] directly from fragments (off-diagonal only)
    if (!diag) {
        bool nedge = (n0 + 127 >= NN);   // m side always interior (bym <= 77)
        #pragma unroll
        for (int i = 0; i < 4; ++i) {
            int rr = wm * 64 + i * 16 + frow;
            size_t m1 = (size_t)(m0 + rr);
            size_t m2 = (size_t)(m0 + rr + 8);
            #pragma unroll
            for (int j = 0; j < 4; ++j) {
                int c = wn * 32 + j * 8 + fcol;
                size_t n1 = (size_t)(n0 + c), n2 = (size_t)(n0 + c + 1);
                if (!nedge) {
                    out[n1 * NN + m1] = acc[i][j][0];
                    out[n2 * NN + m1] = acc[i][j][1];
                    out[n1 * NN + m2] = acc[i][j][2];
                    out[n2 * NN + m2] = acc[i][j][3];
                } else {
                    if (n1 < NN) { out[n1 * NN + m1] = acc[i][j][0];
                                   out[n1 * NN + m2] = acc[i][j][2]; }
                    if (n2 < NN) { out[n2 * NN + m1] = acc[i][j][1];
                                   out[n2 * NN + m2] = acc[i][j][3]; }
                }
            }
        }
    }
}

// ============================================================================
extern "C" void kernel_launch(void* const* d_in, const int* in_sizes, int n_in,
                              void* d_out, int out_size) {
    const float* h  = (const float*)d_in[0];
    const float* W  = (const float*)d_in[1];
    const float* b  = (const float*)d_in[2];
    const int*   es = (const int*)d_in[3];
    const int*   ed = (const int*)d_in[4];
    float*       out = (float*)d_out;

    const size_t smem_hw = (size_t)2 * 128 * TS_STRIDE * sizeof(float);
    cudaFuncSetAttribute(gemm_hw_count_kernel,
                         cudaFuncAttributeMaxDynamicSharedMemorySize, (int)smem_hw);
    cudaFuncSetAttribute(xxt_mma_kernel,
                         cudaFuncAttributeMaxDynamicSharedMemorySize, SMEM_XXT_BYTES);

    gemm_hw_count_kernel<<<HW_BLOCKS + CNT_BLOCKS, 512, smem_hw>>>(h, W, ed);
    csr_scan_kernel<<<1, 1024>>>();
    csr_fill_kernel<<<(NE4 + 255) / 256, 256>>>(es, ed);
    gather_fuse_kernel<<<NPAD, 128>>>(b);
    xxt_mma_kernel<<<3160, 256, SMEM_XXT_BYTES>>>(out);
}

// round 14
// speedup vs baseline: 1.6374x; 1.0315x over previous
#include <cuda_runtime.h>
#include <cuda_fp16.h>
#include <cstdint>
#include <math.h>

#define NN 10000
#define NE 320000
#define NH 128
#define NPAD 10112            // 79 * 128
#define XT_STRIDE 136         // f16 tile stride (halfs): 272B/row == 16 mod 128
#define RS (XT_STRIDE * 2)    // row stride in bytes

// ---------------- scratch ----------------------------------------------------
// INVARIANTS per kernel_launch call: g_deg all-zero (count++ / fill-- self-reset);
// g_scan_flag zeroed by the hw+count launch before scan_fill sets it.
__device__ __half g_hw[(size_t)NN * NH];     // fp16 hw = h@W
__device__ __half g_y[(size_t)NPAD * NH];    // fp16(x), zero-padded
__device__ int g_deg[NN];
__device__ int g_off[NN + 1];
__device__ int g_csr[NE];
__device__ int g_scan_flag;

#define TILE_BYTES (128 * RS)                 // 34816
#define SMEM_2TILE (2 * TILE_BYTES)           // 69632

// ---------------- shared PTX helpers -----------------------------------------
__device__ __forceinline__ uint32_t smem_u32_of(const void* p) {
    uint32_t a;
    asm("{ .reg .u64 t; cvta.to.shared.u64 t, %1; cvt.u32.u64 %0, t; }"
        : "=r"(a) : "l"(p));
    return a;
}
__device__ __forceinline__ void ldsm_x4(uint32_t r[4], uint32_t addr) {
    asm volatile("ldmatrix.sync.aligned.m8n8.x4.shared.b16 {%0,%1,%2,%3}, [%4];"
                 : "=r"(r[0]), "=r"(r[1]), "=r"(r[2]), "=r"(r[3]) : "r"(addr));
}
__device__ __forceinline__ void cp16(uint32_t dst, const void* src) {
    asm volatile("cp.async.cg.shared.global [%0], [%1], 16;" :: "r"(dst), "l"(src));
}
#define CP_COMMIT() asm volatile("cp.async.commit_group;" ::: "memory")
#define CP_WAIT()   asm volatile("cp.async.wait_all;" ::: "memory")
__device__ __forceinline__ void mma_f32acc(float d[4], const uint32_t a[4],
                                           uint32_t b0, uint32_t b1) {
    asm volatile(
        "mma.sync.aligned.m16n8k16.row.col.f32.f16.f16.f32 "
        "{%0,%1,%2,%3}, {%4,%5,%6,%7}, {%8,%9}, {%0,%1,%2,%3};"
        : "+f"(d[0]), "+f"(d[1]), "+f"(d[2]), "+f"(d[3])
        : "r"(a[0]), "r"(a[1]), "r"(a[2]), "r"(a[3]), "r"(b0), "r"(b1));
}

// ============================================================================
// hw = h @ W via HMMA (blocks [0,79), 256 thr) + CONCURRENT degree count
#define HW_BLOCKS 79
#define CNT_BLOCKS 40
#define NE4 (NE / 4)                         // 80000 int4 chunks
extern "C" __global__ void __launch_bounds__(256)
gemm_hw_count_kernel(const float* __restrict__ h, const float* __restrict__ W,
                     const int* __restrict__ ed) {
    if (blockIdx.x >= HW_BLOCKS) {
        if (blockIdx.x == HW_BLOCKS && threadIdx.x == 0) g_scan_flag = 0;
        int gtid = (blockIdx.x - HW_BLOCKS) * 256 + threadIdx.x;  // < 10240
        const int4* ed4 = (const int4*)ed;
        for (int c = gtid; c < NE4; c += CNT_BLOCKS * 256) {
            int4 d4 = ed4[c];
            atomicAdd(&g_deg[d4.x], 1);
            atomicAdd(&g_deg[d4.y], 1);
            atomicAdd(&g_deg[d4.z], 1);
            atomicAdd(&g_deg[d4.w], 1);
        }
        return;
    }
    extern __shared__ char smem[];
    uint32_t uA = smem_u32_of(smem);           // h tile fp16 [m][k]
    uint32_t uB = uA + TILE_BYTES;             // W^T fp16 [n][k]
    __half* Bt = (__half*)(smem + TILE_BYTES);
    int tid = threadIdx.x;
    int row0 = blockIdx.x * 128;

    // load h tile -> fp16 [m][k]; zero-pad rows >= NN
    #pragma unroll
    for (int it = 0; it < 8; ++it) {
        int chunk = it * 256 + tid;            // 2048 chunks of 8 elems
        int row = chunk >> 4, c8 = chunk & 15;
        int m = row0 + row;
        float4 v0 = make_float4(0.f, 0.f, 0.f, 0.f), v1 = v0;
        if (m < NN) {
            const float* p = h + (size_t)m * NH + c8 * 8;
            v0 = *(const float4*)p;
            v1 = *(const float4*)(p + 4);
        }
        __half2* dst = (__half2*)(smem + row * RS + c8 * 16);
        dst[0] = __floats2half2_rn(v0.x, v0.y);
        dst[1] = __floats2half2_rn(v0.z, v0.w);
        dst[2] = __floats2half2_rn(v1.x, v1.y);
        dst[3] = __floats2half2_rn(v1.z, v1.w);
    }
    // load W transposed -> fp16 [n][k] (coalesced f32 reads, strided 2B STS)
    #pragma unroll 8
    for (int it = 0; it < 64; ++it) {
        int idx = it * 256 + tid;              // 16384
        int n = idx & 127, k = idx >> 7;
        Bt[n * XT_STRIDE + k] = __float2half_rn(W[k * NH + n]);
    }
    __syncthreads();

    int lane = tid & 31, wid = tid >> 5;
    int wm = wid & 1, wn = wid >> 1;
    int frow = lane >> 2, fcol = 2 * (lane & 3);
    uint32_t laneA = (uint32_t)((lane & 15) * RS + (lane >> 4) * 16);
    uint32_t laneB = (uint32_t)((((lane >> 4) & 1) * 8 + (lane & 7)) * RS
                                + ((lane >> 3) & 1) * 16);
    float acc[4][4][4] = {};
    #pragma unroll
    for (int k0 = 0; k0 < 8; ++k0) {
        uint32_t kb = k0 * 32;
        uint32_t bf[2][4];
        #pragma unroll
        for (int jp = 0; jp < 2; ++jp)
            ldsm_x4(bf[jp], uB + laneB + (uint32_t)((wn * 32 + jp * 16) * RS) + kb);
        #pragma unroll
        for (int i = 0; i < 4; ++i) {
            uint32_t a[4];
            ldsm_x4(a, uA + laneA + (uint32_t)((wm * 64 + i * 16) * RS) + kb);
            #pragma unroll
            for (int jp = 0; jp < 2; ++jp) {
                mma_f32acc(acc[i][2 * jp],     a, bf[jp][0], bf[jp][1]);
                mma_f32acc(acc[i][2 * jp + 1], a, bf[jp][2], bf[jp][3]);
            }
        }
    }
    #pragma unroll
    for (int i = 0; i < 4; ++i) {
        int rr = wm * 64 + i * 16 + frow;
        int m1 = row0 + rr, m2 = m1 + 8;
        #pragma unroll
        for (int j = 0; j < 4; ++j) {
            int c = wn * 32 + j * 8 + fcol;
            if (m1 < NN)
                *(__half2*)&g_hw[(size_t)m1 * NH + c] =
                    __floats2half2_rn(acc[i][j][0], acc[i][j][1]);
            if (m2 < NN)
                *(__half2*)&g_hw[(size_t)m2 * NH + c] =
                    __floats2half2_rn(acc[i][j][2], acc[i][j][3]);
        }
    }
}

// ============================================================================
// fused scan (block 0) + fill (all blocks, after acquire-spin on flag)
extern "C" __global__ void __launch_bounds__(256)
scan_fill_kernel(const int* __restrict__ es, const int* __restrict__ ed) {
    int tid = threadIdx.x;
    if (blockIdx.x == 0) {
        __shared__ int part[256];
        int base = tid * 40;                 // 250 threads cover 10000
        int s = 0;
        #pragma unroll
        for (int q = 0; q < 40; ++q) { int i = base + q; if (i < NN) s += g_deg[i]; }
        part[tid] = s;
        __syncthreads();
        #pragma unroll
        for (int off = 1; off < 256; off <<= 1) {
            int v = (tid >= off) ? part[tid - off] : 0;
            __syncthreads();
            part[tid] += v;
            __syncthreads();
        }
        int run = (tid == 0) ? 0 : part[tid - 1];
        #pragma unroll
        for (int q = 0; q < 40; ++q) {
            int i = base + q;
            if (i < NN) { g_off[i] = run; run += g_deg[i]; }
        }
        if (tid == 0) g_off[NN] = part[255];
        __threadfence();
        __syncthreads();
        if (tid == 0) atomicExch(&g_scan_flag, 1);
    } else {
        if (tid == 0) { while (atomicAdd(&g_scan_flag, 0) == 0) {} }
        __syncthreads();
        __threadfence();
    }
    // fill: atomicSub drains g_deg back to zero (self-reset invariant)
    int i = blockIdx.x * 256 + tid;          // grid covers NE4
    if (i < NE4) {
        int4 s4 = ((const int4*)es)[i];
        int4 d4 = ((const int4*)ed)[i];
        int o0 = atomicSub(&g_deg[d4.x], 1);
        int o1 = atomicSub(&g_deg[d4.y], 1);
        int o2 = atomicSub(&g_deg[d4.z], 1);
        int o3 = atomicSub(&g_deg[d4.w], 1);
        g_csr[g_off[d4.x] + o0 - 1] = s4.x;
        g_csr[g_off[d4.y] + o1 - 1] = s4.y;
        g_csr[g_off[d4.z] + o2 - 1] = s4.z;
        g_csr[g_off[d4.w] + o3 - 1] = s4.w;
    }
}

// ============================================================================
// gather + bias + relu + fp16 quantize — HADD2 pair reduction (issue diet)
extern "C" __global__ void __launch_bounds__(128)
gather_fuse_kernel(const float* __restrict__ b) {
    __shared__ float sred[4 * NH];           // 4 warps x 128 channels
    int node = blockIdx.x;
    int tid = threadIdx.x;
    int quad = tid >> 5, lane = tid & 31;
    int c4 = lane << 2;

    if (node >= NN) {
        if (tid < NH) g_y[(size_t)node * NH + tid] = __float2half(0.0f);
        return;
    }
    int beg = g_off[node];
    int end = g_off[node + 1];

    float4 a4 = make_float4(0.f, 0.f, 0.f, 0.f);
    int e = beg + quad;
    for (; e + 4 < end; e += 8) {
        int s0 = g_csr[e];
        int s1 = g_csr[e + 4];
        uint2 u0 = *(const uint2*)&g_hw[(size_t)s0 * NH + c4];
        uint2 u1 = *(const uint2*)&g_hw[(size_t)s1 * NH + c4];
        __half2 p0 = __hadd2(*(__half2*)&u0.x, *(__half2*)&u1.x);
        __half2 p1 = __hadd2(*(__half2*)&u0.y, *(__half2*)&u1.y);
        float2 f0 = __half22float2(p0);
        float2 f1 = __half22float2(p1);
        a4.x += f0.x; a4.y += f0.y; a4.z += f1.x; a4.w += f1.y;
    }
    if (e < end) {
        int s0 = g_csr[e];
        uint2 u0 = *(const uint2*)&g_hw[(size_t)s0 * NH + c4];
        float2 f0 = __half22float2(*(__half2*)&u0.x);
        float2 f1 = __half22float2(*(__half2*)&u0.y);
        a4.x += f0.x; a4.y += f0.y; a4.z += f1.x; a4.w += f1.y;
    }
    *(float4*)&sred[quad * NH + c4] = a4;
    __syncthreads();

    int c = tid;
    float v = sred[c] + sred[NH + c] + sred[2 * NH + c] + sred[3 * NH + c];
    v += b[c];
    v = v > 0.0f ? v : 0.0f;
    g_y[(size_t)node * NH + c] = __float2half_rn(v);
}

// ============================================================================
// xxt = y @ y^T — UNCHANGED (protected win; at DRAM-write floor)
#define SMEM_XXT_BYTES SMEM_2TILE             // 69632 -> occ 2

__device__ __forceinline__ void load_tile_async(const __half* __restrict__ src,
                                                int row0, uint32_t dst) {
    int tid = threadIdx.x;  // 256 threads, 8 x 16B each
    #pragma unroll
    for (int it = 0; it < 8; ++it) {
        int chunk = it * 256 + tid;
        int row = chunk >> 4, c16 = chunk & 15;
        cp16(dst + row * RS + c16 * 16,
             src + (size_t)(row0 + row) * NH + c16 * 8);
    }
}

extern "C" __global__ void __launch_bounds__(256, 2)
xxt_mma_kernel(float* __restrict__ out) {
    // triangular decode: t -> (bym, bxn), bym <= bxn, 79x79 upper triangle
    int t = blockIdx.x;
    int r = (int)((159.0f - sqrtf(25281.0f - 8.0f * (float)t)) * 0.5f);
    if (r < 0) r = 0; if (r > 78) r = 78;
    while ((r + 1) * 79 - ((r + 1) * r) / 2 <= t) ++r;
    while (r * 79 - (r * (r - 1)) / 2 > t) --r;
    int bym = r;
    int bxn = r + (t - (r * 79 - (r * (r - 1)) / 2));
    bool diag = (bxn == bym);

    extern __shared__ char smem[];
    uint32_t uA = smem_u32_of(smem);
    uint32_t uB = uA + TILE_BYTES;

    load_tile_async(g_y, bym * 128, uA);
    if (!diag) load_tile_async(g_y, bxn * 128, uB);
    else       uB = uA;
    CP_COMMIT(); CP_WAIT();
    __syncthreads();

    int tid = threadIdx.x, lane = tid & 31, wid = tid >> 5;
    int wm = wid & 1;
    int wn = wid >> 1;
    int frow = lane >> 2;
    int fcol = 2 * (lane & 3);
    uint32_t laneA = (uint32_t)((lane & 15) * RS + (lane >> 4) * 16);
    uint32_t laneB = (uint32_t)((((lane >> 4) & 1) * 8 + (lane & 7)) * RS
                                + ((lane >> 3) & 1) * 16);

    float acc[4][4][4] = {};

    #pragma unroll
    for (int k0 = 0; k0 < 8; ++k0) {
        uint32_t kb = k0 * 32;
        uint32_t bf[2][4];
        #pragma unroll
        for (int jp = 0; jp < 2; ++jp)
            ldsm_x4(bf[jp], uB + laneB + (uint32_t)((wn * 32 + jp * 16) * RS) + kb);
        #pragma unroll
        for (int i = 0; i < 4; ++i) {
            uint32_t a[4];
            ldsm_x4(a, uA + laneA + (uint32_t)((wm * 64 + i * 16) * RS) + kb);
            #pragma unroll
            for (int jp = 0; jp < 2; ++jp) {
                mma_f32acc(acc[i][2 * jp],     a, bf[jp][0], bf[jp][1]);
                mma_f32acc(acc[i][2 * jp + 1], a, bf[jp][2], bf[jp][3]);
            }
        }
    }

    int m0 = bym * 128, n0 = bxn * 128;
    bool edge = (n0 + 127 >= NN) || (m0 + 127 >= NN);

    // main-tile store C[m][n] (float2, default policy — L2 write-combines)
    #pragma unroll
    for (int i = 0; i < 4; ++i) {
        int rr = wm * 64 + i * 16 + frow;
        #pragma unroll
        for (int j = 0; j < 4; ++j) {
            int c = wn * 32 + j * 8 + fcol;
            if (!edge) {
                *(float2*)&out[(size_t)(m0 + rr) * NN + n0 + c] =
                    make_float2(acc[i][j][0], acc[i][j][1]);
                *(float2*)&out[(size_t)(m0 + rr + 8) * NN + n0 + c] =
                    make_float2(acc[i][j][2], acc[i][j][3]);
            } else {
                int m1 = m0 + rr, m2 = m0 + rr + 8, n = n0 + c;
                if (m1 < NN) {
                    if (n < NN)     out[(size_t)m1 * NN + n]     = acc[i][j][0];
                    if (n + 1 < NN) out[(size_t)m1 * NN + n + 1] = acc[i][j][1];
                }
                if (m2 < NN) {
                    if (n < NN)     out[(size_t)m2 * NN + n]     = acc[i][j][2];
                    if (n + 1 < NN) out[(size_t)m2 * NN + n + 1] = acc[i][j][3];
                }
            }
        }
    }

    // mirror store C[n][m] directly from fragments (off-diagonal only)
    if (!diag) {
        bool nedge = (n0 + 127 >= NN);   // m side always interior (bym <= 77)
        #pragma unroll
        for (int i = 0; i < 4; ++i) {
            int rr = wm * 64 + i * 16 + frow;
            size_t m1 = (size_t)(m0 + rr);
            size_t m2 = (size_t)(m0 + rr + 8);
            #pragma unroll
            for (int j = 0; j < 4; ++j) {
                int c = wn * 32 + j * 8 + fcol;
                size_t n1 = (size_t)(n0 + c), n2 = (size_t)(n0 + c + 1);
                if (!nedge) {
                    out[n1 * NN + m1] = acc[i][j][0];
                    out[n2 * NN + m1] = acc[i][j][1];
                    out[n1 * NN + m2] = acc[i][j][2];
                    out[n2 * NN + m2] = acc[i][j][3];
                } else {
                    if (n1 < NN) { out[n1 * NN + m1] = acc[i][j][0];
                                   out[n1 * NN + m2] = acc[i][j][2]; }
                    if (n2 < NN) { out[n2 * NN + m1] = acc[i][j][1];
                                   out[n2 * NN + m2] = acc[i][j][3]; }
                }
            }
        }
    }
}

// ============================================================================
extern "C" void kernel_launch(void* const* d_in, const int* in_sizes, int n_in,
                              void* d_out, int out_size) {
    const float* h  = (const float*)d_in[0];
    const float* W  = (const float*)d_in[1];
    const float* b  = (const float*)d_in[2];
    const int*   es = (const int*)d_in[3];
    const int*   ed = (const int*)d_in[4];
    float*       out = (float*)d_out;

    cudaFuncSetAttribute(gemm_hw_count_kernel,
                         cudaFuncAttributeMaxDynamicSharedMemorySize, SMEM_2TILE);
    cudaFuncSetAttribute(xxt_mma_kernel,
                         cudaFuncAttributeMaxDynamicSharedMemorySize, SMEM_XXT_BYTES);

    gemm_hw_count_kernel<<<HW_BLOCKS + CNT_BLOCKS, 256, SMEM_2TILE>>>(h, W, ed);
    scan_fill_kernel<<<(NE4 + 255) / 256, 256>>>(es, ed);
    gather_fuse_kernel<<<NPAD, 128>>>(b);
    xxt_mma_kernel<<<3160, 256, SMEM_XXT_BYTES>>>(out);
}

// round 15
// speedup vs baseline: 1.7137x; 1.0466x over previous
#include <cuda_runtime.h>
#include <cuda_fp16.h>
#include <cstdint>
#include <math.h>

#define NN 10000
#define NE 320000
#define NH 128
#define NPAD 10112            // 79 * 128
#define XT_STRIDE 136         // f16 tile stride (halfs): 272B/row == 16 mod 128
#define RS (XT_STRIDE * 2)    // row stride in bytes

// ---------------- scratch ----------------------------------------------------
// INVARIANTS per kernel_launch call: g_deg all-zero (count++ / fill-- self-reset);
// g_scan_flag zeroed by the hw+count launch before scan_fill sets it.
__device__ __half g_hw[(size_t)NN * NH];     // fp16 hw = h@W
__device__ __half g_y[(size_t)NPAD * NH];    // fp16(x), zero-padded
__device__ int g_deg[NN];
__device__ int g_off[NN + 1];
__device__ int g_csr[NE];
__device__ int g_scan_flag;

#define TILE_BYTES (128 * RS)                 // 34816
#define SMEM_2TILE (2 * TILE_BYTES)           // 69632
#define SMEM_3TILE (3 * TILE_BYTES)           // 104448

// ---------------- shared PTX helpers -----------------------------------------
__device__ __forceinline__ uint32_t smem_u32_of(const void* p) {
    uint32_t a;
    asm("{ .reg .u64 t; cvta.to.shared.u64 t, %1; cvt.u32.u64 %0, t; }"
        : "=r"(a) : "l"(p));
    return a;
}
__device__ __forceinline__ void ldsm_x4(uint32_t r[4], uint32_t addr) {
    asm volatile("ldmatrix.sync.aligned.m8n8.x4.shared.b16 {%0,%1,%2,%3}, [%4];"
                 : "=r"(r[0]), "=r"(r[1]), "=r"(r[2]), "=r"(r[3]) : "r"(addr));
}
__device__ __forceinline__ void cp16(uint32_t dst, const void* src) {
    asm volatile("cp.async.cg.shared.global [%0], [%1], 16;" :: "r"(dst), "l"(src));
}
#define CP_COMMIT() asm volatile("cp.async.commit_group;" ::: "memory")
#define CP_WAIT()   asm volatile("cp.async.wait_all;" ::: "memory")
__device__ __forceinline__ void mma_f32acc(float d[4], const uint32_t a[4],
                                           uint32_t b0, uint32_t b1) {
    asm volatile(
        "mma.sync.aligned.m16n8k16.row.col.f32.f16.f16.f32 "
        "{%0,%1,%2,%3}, {%4,%5,%6,%7}, {%8,%9}, {%0,%1,%2,%3};"
        : "+f"(d[0]), "+f"(d[1]), "+f"(d[2]), "+f"(d[3])
        : "r"(a[0]), "r"(a[1]), "r"(a[2]), "r"(a[3]), "r"(b0), "r"(b1));
}

// ============================================================================
// hw = h @ W via HMMA (blocks [0,79), 256 thr) + CONCURRENT degree count
#define HW_BLOCKS 79
#define CNT_BLOCKS 40
#define NE4 (NE / 4)                         // 80000 int4 chunks
extern "C" __global__ void __launch_bounds__(256)
gemm_hw_count_kernel(const float* __restrict__ h, const float* __restrict__ W,
                     const int* __restrict__ ed) {
    if (blockIdx.x >= HW_BLOCKS) {
        if (blockIdx.x == HW_BLOCKS && threadIdx.x == 0) g_scan_flag = 0;
        int gtid = (blockIdx.x - HW_BLOCKS) * 256 + threadIdx.x;  // < 10240
        const int4* ed4 = (const int4*)ed;
        for (int c = gtid; c < NE4; c += CNT_BLOCKS * 256) {
            int4 d4 = ed4[c];
            atomicAdd(&g_deg[d4.x], 1);
            atomicAdd(&g_deg[d4.y], 1);
            atomicAdd(&g_deg[d4.z], 1);
            atomicAdd(&g_deg[d4.w], 1);
        }
        return;
    }
    extern __shared__ char smem[];
    uint32_t uA = smem_u32_of(smem);           // h tile fp16 [m][k]
    uint32_t uB = uA + TILE_BYTES;             // W^T fp16 [n][k]
    __half* Bt = (__half*)(smem + TILE_BYTES);
    int tid = threadIdx.x;
    int row0 = blockIdx.x * 128;

    #pragma unroll
    for (int it = 0; it < 8; ++it) {
        int chunk = it * 256 + tid;
        int row = chunk >> 4, c8 = chunk & 15;
        int m = row0 + row;
        float4 v0 = make_float4(0.f, 0.f, 0.f, 0.f), v1 = v0;
        if (m < NN) {
            const float* p = h + (size_t)m * NH + c8 * 8;
            v0 = *(const float4*)p;
            v1 = *(const float4*)(p + 4);
        }
        __half2* dst = (__half2*)(smem + row * RS + c8 * 16);
        dst[0] = __floats2half2_rn(v0.x, v0.y);
        dst[1] = __floats2half2_rn(v0.z, v0.w);
        dst[2] = __floats2half2_rn(v1.x, v1.y);
        dst[3] = __floats2half2_rn(v1.z, v1.w);
    }
    #pragma unroll 8
    for (int it = 0; it < 64; ++it) {
        int idx = it * 256 + tid;
        int n = idx & 127, k = idx >> 7;
        Bt[n * XT_STRIDE + k] = __float2half_rn(W[k * NH + n]);
    }
    __syncthreads();

    int lane = tid & 31, wid = tid >> 5;
    int wm = wid & 1, wn = wid >> 1;
    int frow = lane >> 2, fcol = 2 * (lane & 3);
    uint32_t laneA = (uint32_t)((lane & 15) * RS + (lane >> 4) * 16);
    uint32_t laneB = (uint32_t)((((lane >> 4) & 1) * 8 + (lane & 7)) * RS
                                + ((lane >> 3) & 1) * 16);
    float acc[4][4][4] = {};
    #pragma unroll
    for (int k0 = 0; k0 < 8; ++k0) {
        uint32_t kb = k0 * 32;
        uint32_t bf[2][4];
        #pragma unroll
        for (int jp = 0; jp < 2; ++jp)
            ldsm_x4(bf[jp], uB + laneB + (uint32_t)((wn * 32 + jp * 16) * RS) + kb);
        #pragma unroll
        for (int i = 0; i < 4; ++i) {
            uint32_t a[4];
            ldsm_x4(a, uA + laneA + (uint32_t)((wm * 64 + i * 16) * RS) + kb);
            #pragma unroll
            for (int jp = 0; jp < 2; ++jp) {
                mma_f32acc(acc[i][2 * jp],     a, bf[jp][0], bf[jp][1]);
                mma_f32acc(acc[i][2 * jp + 1], a, bf[jp][2], bf[jp][3]);
            }
        }
    }
    #pragma unroll
    for (int i = 0; i < 4; ++i) {
        int rr = wm * 64 + i * 16 + frow;
        int m1 = row0 + rr, m2 = m1 + 8;
        #pragma unroll
        for (int j = 0; j < 4; ++j) {
            int c = wn * 32 + j * 8 + fcol;
            if (m1 < NN)
                *(__half2*)&g_hw[(size_t)m1 * NH + c] =
                    __floats2half2_rn(acc[i][j][0], acc[i][j][1]);
            if (m2 < NN)
                *(__half2*)&g_hw[(size_t)m2 * NH + c] =
                    __floats2half2_rn(acc[i][j][2], acc[i][j][3]);
        }
    }
}

// ============================================================================
// fused scan (block 0) + fill (all blocks, acquire-spin)
extern "C" __global__ void __launch_bounds__(256)
scan_fill_kernel(const int* __restrict__ es, const int* __restrict__ ed) {
    int tid = threadIdx.x;
    if (blockIdx.x == 0) {
        __shared__ int part[256];
        int base = tid * 40;
        int s = 0;
        #pragma unroll
        for (int q = 0; q < 40; ++q) { int i = base + q; if (i < NN) s += g_deg[i]; }
        part[tid] = s;
        __syncthreads();
        #pragma unroll
        for (int off = 1; off < 256; off <<= 1) {
            int v = (tid >= off) ? part[tid - off] : 0;
            __syncthreads();
            part[tid] += v;
            __syncthreads();
        }
        int run = (tid == 0) ? 0 : part[tid - 1];
        #pragma unroll
        for (int q = 0; q < 40; ++q) {
            int i = base + q;
            if (i < NN) { g_off[i] = run; run += g_deg[i]; }
        }
        if (tid == 0) g_off[NN] = part[255];
        __threadfence();
        __syncthreads();
        if (tid == 0) atomicExch(&g_scan_flag, 1);
    } else {
        if (tid == 0) { while (atomicAdd(&g_scan_flag, 0) == 0) {} }
        __syncthreads();
        __threadfence();
    }
    int i = blockIdx.x * 256 + tid;
    if (i < NE4) {
        int4 s4 = ((const int4*)es)[i];
        int4 d4 = ((const int4*)ed)[i];
        int o0 = atomicSub(&g_deg[d4.x], 1);
        int o1 = atomicSub(&g_deg[d4.y], 1);
        int o2 = atomicSub(&g_deg[d4.z], 1);
        int o3 = atomicSub(&g_deg[d4.w], 1);
        g_csr[g_off[d4.x] + o0 - 1] = s4.x;
        g_csr[g_off[d4.y] + o1 - 1] = s4.y;
        g_csr[g_off[d4.z] + o2 - 1] = s4.z;
        g_csr[g_off[d4.w] + o3 - 1] = s4.w;
    }
}

// ============================================================================
// gather + bias + relu + fp16 quantize — HADD2 pair reduction
extern "C" __global__ void __launch_bounds__(128)
gather_fuse_kernel(const float* __restrict__ b) {
    __shared__ float sred[4 * NH];
    int node = blockIdx.x;
    int tid = threadIdx.x;
    int quad = tid >> 5, lane = tid & 31;
    int c4 = lane << 2;

    if (node >= NN) {
        if (tid < NH) g_y[(size_t)node * NH + tid] = __float2half(0.0f);
        return;
    }
    int beg = g_off[node];
    int end = g_off[node + 1];

    float4 a4 = make_float4(0.f, 0.f, 0.f, 0.f);
    int e = beg + quad;
    for (; e + 4 < end; e += 8) {
        int s0 = g_csr[e];
        int s1 = g_csr[e + 4];
        uint2 u0 = *(const uint2*)&g_hw[(size_t)s0 * NH + c4];
        uint2 u1 = *(const uint2*)&g_hw[(size_t)s1 * NH + c4];
        __half2 p0 = __hadd2(*(__half2*)&u0.x, *(__half2*)&u1.x);
        __half2 p1 = __hadd2(*(__half2*)&u0.y, *(__half2*)&u1.y);
        float2 f0 = __half22float2(p0);
        float2 f1 = __half22float2(p1);
        a4.x += f0.x; a4.y += f0.y; a4.z += f1.x; a4.w += f1.y;
    }
    if (e < end) {
        int s0 = g_csr[e];
        uint2 u0 = *(const uint2*)&g_hw[(size_t)s0 * NH + c4];
        float2 f0 = __half22float2(*(__half2*)&u0.x);
        float2 f1 = __half22float2(*(__half2*)&u0.y);
        a4.x += f0.x; a4.y += f0.y; a4.z += f1.x; a4.w += f1.y;
    }
    *(float4*)&sred[quad * NH + c4] = a4;
    __syncthreads();

    int c = tid;
    float v = sred[c] + sred[NH + c] + sred[2 * NH + c] + sred[3 * NH + c];
    v += b[c];
    v = v > 0.0f ? v : 0.0f;
    g_y[(size_t)node * NH + c] = __float2half_rn(v);
}

// ============================================================================
// xxt = y @ y^T — strip-persistent: 296 CTAs, A reused per strip, B prefetched
#define XXT_CTAS 296
#define T_TILES 3160

__device__ __forceinline__ void load_tile_async(const __half* __restrict__ src,
                                                int row0, uint32_t dst) {
    int tid = threadIdx.x;  // 256 threads, 8 x 16B each
    #pragma unroll
    for (int it = 0; it < 8; ++it) {
        int chunk = it * 256 + tid;
        int row = chunk >> 4, c16 = chunk & 15;
        cp16(dst + row * RS + c16 * 16,
             src + (size_t)(row0 + row) * NH + c16 * 8);
    }
}

extern "C" __global__ void __launch_bounds__(256, 2)
xxt_mma_kernel(float* __restrict__ out) {
    int g = blockIdx.x;
    // balanced chunks: CTAs [0,200) take 11 tiles, [200,296) take 10
    int t0   = g * 10 + (g < 200 ? g : 200);
    int tend = t0 + (g < 200 ? 11 : 10);
    if (tend > T_TILES) tend = T_TILES;
    if (t0 >= tend) return;

    // decode t0 -> (bym, bxn), row-major upper triangle of 79x79
    int r = (int)((159.0f - sqrtf(25281.0f - 8.0f * (float)t0)) * 0.5f);
    if (r < 0) r = 0; if (r > 78) r = 78;
    while ((r + 1) * 79 - ((r + 1) * r) / 2 <= t0) ++r;
    while (r * 79 - (r * (r - 1)) / 2 > t0) --r;
    int bym = r;
    int bxn = r + (t0 - (r * 79 - (r * (r - 1)) / 2));

    extern __shared__ char smem[];
    uint32_t uA = smem_u32_of(smem);

    int tid = threadIdx.x, lane = tid & 31, wid = tid >> 5;
    int wm = wid & 1, wn = wid >> 1;
    int frow = lane >> 2, fcol = 2 * (lane & 3);
    uint32_t laneA = (uint32_t)((lane & 15) * RS + (lane >> 4) * 16);
    uint32_t laneB = (uint32_t)((((lane >> 4) & 1) * 8 + (lane & 7)) * RS
                                + ((lane >> 3) & 1) * 16);

    // prologue loads: A(bym) and, if non-diag, B(bxn)
    bool diag = (bxn == bym);
    load_tile_async(g_y, bym * 128, uA);
    if (!diag) load_tile_async(g_y, bxn * 128, uA + TILE_BYTES * (1 + (t0 & 1)));
    CP_COMMIT(); CP_WAIT();
    __syncthreads();

    for (int t = t0; t < tend; ++t) {
        // next-tile coordinates (row-major walk)
        int bymN = bym, bxnN = bxn + 1;
        if (bxnN > 78) { bymN = bym + 1; bxnN = bymN; }
        bool can_pf = (t + 1 < tend) && (bymN == bym);   // same strip -> non-diag B
        if (can_pf) {
            load_tile_async(g_y, bxnN * 128, uA + TILE_BYTES * (1 + ((t + 1) & 1)));
            CP_COMMIT();
        }

        uint32_t uB = diag ? uA : (uA + TILE_BYTES * (1 + (t & 1)));

        float acc[4][4][4] = {};
        #pragma unroll
        for (int k0 = 0; k0 < 8; ++k0) {
            uint32_t kb = k0 * 32;
            uint32_t bf[2][4];
            #pragma unroll
            for (int jp = 0; jp < 2; ++jp)
                ldsm_x4(bf[jp], uB + laneB + (uint32_t)((wn * 32 + jp * 16) * RS) + kb);
            #pragma unroll
            for (int i = 0; i < 4; ++i) {
                uint32_t a[4];
                ldsm_x4(a, uA + laneA + (uint32_t)((wm * 64 + i * 16) * RS) + kb);
                #pragma unroll
                for (int jp = 0; jp < 2; ++jp) {
                    mma_f32acc(acc[i][2 * jp],     a, bf[jp][0], bf[jp][1]);
                    mma_f32acc(acc[i][2 * jp + 1], a, bf[jp][2], bf[jp][3]);
                }
            }
        }

        int m0 = bym * 128, n0 = bxn * 128;
        bool edge = (n0 + 127 >= NN) || (m0 + 127 >= NN);

        // main-tile store C[m][n]
        #pragma unroll
        for (int i = 0; i < 4; ++i) {
            int rr = wm * 64 + i * 16 + frow;
            #pragma unroll
            for (int j = 0; j < 4; ++j) {
                int c = wn * 32 + j * 8 + fcol;
                if (!edge) {
                    *(float2*)&out[(size_t)(m0 + rr) * NN + n0 + c] =
                        make_float2(acc[i][j][0], acc[i][j][1]);
                    *(float2*)&out[(size_t)(m0 + rr + 8) * NN + n0 + c] =
                        make_float2(acc[i][j][2], acc[i][j][3]);
                } else {
                    int m1 = m0 + rr, m2 = m0 + rr + 8, n = n0 + c;
                    if (m1 < NN) {
                        if (n < NN)     out[(size_t)m1 * NN + n]     = acc[i][j][0];
                        if (n + 1 < NN) out[(size_t)m1 * NN + n + 1] = acc[i][j][1];
                    }
                    if (m2 < NN) {
                        if (n < NN)     out[(size_t)m2 * NN + n]     = acc[i][j][2];
                        if (n + 1 < NN) out[(size_t)m2 * NN + n + 1] = acc[i][j][3];
                    }
                }
            }
        }
        // mirror store C[n][m]
        if (!diag) {
            bool nedge = (n0 + 127 >= NN);
            #pragma unroll
            for (int i = 0; i < 4; ++i) {
                int rr = wm * 64 + i * 16 + frow;
                size_t m1 = (size_t)(m0 + rr);
                size_t m2 = (size_t)(m0 + rr + 8);
                #pragma unroll
                for (int j = 0; j < 4; ++j) {
                    int c = wn * 32 + j * 8 + fcol;
                    size_t n1 = (size_t)(n0 + c), n2 = (size_t)(n0 + c + 1);
                    if (!nedge) {
                        out[n1 * NN + m1] = acc[i][j][0];
                        out[n2 * NN + m1] = acc[i][j][1];
                        out[n1 * NN + m2] = acc[i][j][2];
                        out[n2 * NN + m2] = acc[i][j][3];
                    } else {
                        if (n1 < NN) { out[n1 * NN + m1] = acc[i][j][0];
                                       out[n1 * NN + m2] = acc[i][j][2]; }
                        if (n2 < NN) { out[n2 * NN + m1] = acc[i][j][1];
                                       out[n2 * NN + m2] = acc[i][j][3]; }
                    }
                }
            }
        }

        __syncthreads();   // all warps done reading tiles before any overwrite
        if (t + 1 < tend) {
            if (!can_pf) {  // strip change: next tile is diagonal -> reload A only
                load_tile_async(g_y, bymN * 128, uA);
                CP_COMMIT();
            }
            CP_WAIT();      // prefetch (or A reload) complete
            __syncthreads();
        }
        bym = bymN; bxn = bxnN; diag = (bxnN == bymN);
    }
}

// ============================================================================
extern "C" void kernel_launch(void* const* d_in, const int* in_sizes, int n_in,
                              void* d_out, int out_size) {
    const float* h  = (const float*)d_in[0];
    const float* W  = (const float*)d_in[1];
    const float* b  = (const float*)d_in[2];
    const int*   es = (const int*)d_in[3];
    const int*   ed = (const int*)d_in[4];
    float*       out = (float*)d_out;

    cudaFuncSetAttribute(gemm_hw_count_kernel,
                         cudaFuncAttributeMaxDynamicSharedMemorySize, SMEM_2TILE);
    cudaFuncSetAttribute(xxt_mma_kernel,
                         cudaFuncAttributeMaxDynamicSharedMemorySize, SMEM_3TILE);

    gemm_hw_count_kernel<<<HW_BLOCKS + CNT_BLOCKS, 256, SMEM_2TILE>>>(h, W, ed);
    scan_fill_kernel<<<(NE4 + 255) / 256, 256>>>(es, ed);
    gather_fuse_kernel<<<NPAD, 128>>>(b);
    xxt_mma_kernel<<<XXT_CTAS, 256, SMEM_3TILE>>>(out);
}

// round 16
// speedup vs baseline: 1.7348x; 1.0123x over previous
#include <cuda_runtime.h>
#include <cuda_fp16.h>
#include <cstdint>
#include <math.h>

#define NN 10000
#define NE 320000
#define NH 128
#define NPAD 10112            // 79 * 128
#define XT_STRIDE 136         // f16 tile stride (halfs): 272B/row == 16 mod 128
#define RS (XT_STRIDE * 2)    // row stride in bytes

// ---------------- scratch ----------------------------------------------------
// INVARIANTS per kernel_launch call: g_deg all-zero (count++ / fill-- self-reset);
// g_scan_flag zeroed by the hw+count launch before scan_fill sets it.
__device__ __half g_hw[(size_t)NN * NH];     // fp16 hw = h@W
__device__ __half g_y[(size_t)NPAD * NH];    // fp16(x), zero-padded
__device__ int g_deg[NN];
__device__ int g_off[NN + 1];
__device__ int g_csr[NE];
__device__ int g_scan_flag;

#define TILE_BYTES (128 * RS)                 // 34816
#define SMEM_2TILE (2 * TILE_BYTES)           // 69632
#define SMEM_3TILE (3 * TILE_BYTES)           // 104448

// ---------------- shared PTX helpers -----------------------------------------
__device__ __forceinline__ uint32_t smem_u32_of(const void* p) {
    uint32_t a;
    asm("{ .reg .u64 t; cvta.to.shared.u64 t, %1; cvt.u32.u64 %0, t; }"
        : "=r"(a) : "l"(p));
    return a;
}
__device__ __forceinline__ void ldsm_x4(uint32_t r[4], uint32_t addr) {
    asm volatile("ldmatrix.sync.aligned.m8n8.x4.shared.b16 {%0,%1,%2,%3}, [%4];"
                 : "=r"(r[0]), "=r"(r[1]), "=r"(r[2]), "=r"(r[3]) : "r"(addr));
}
__device__ __forceinline__ void cp16(uint32_t dst, const void* src) {
    asm volatile("cp.async.cg.shared.global [%0], [%1], 16;" :: "r"(dst), "l"(src));
}
#define CP_COMMIT() asm volatile("cp.async.commit_group;" ::: "memory")
#define CP_WAIT()   asm volatile("cp.async.wait_all;" ::: "memory")
__device__ __forceinline__ void mma_f32acc(float d[4], const uint32_t a[4],
                                           uint32_t b0, uint32_t b1) {
    asm volatile(
        "mma.sync.aligned.m16n8k16.row.col.f32.f16.f16.f32 "
        "{%0,%1,%2,%3}, {%4,%5,%6,%7}, {%8,%9}, {%0,%1,%2,%3};"
        : "+f"(d[0]), "+f"(d[1]), "+f"(d[2]), "+f"(d[3])
        : "r"(a[0]), "r"(a[1]), "r"(a[2]), "r"(a[3]), "r"(b0), "r"(b1));
}

// ============================================================================
// hw = h @ W via HMMA (blocks [0,79), 256 thr) + CONCURRENT degree count
#define HW_BLOCKS 79
#define CNT_BLOCKS 40
#define NE4 (NE / 4)                         // 80000 int4 chunks
extern "C" __global__ void __launch_bounds__(256)
gemm_hw_count_kernel(const float* __restrict__ h, const float* __restrict__ W,
                     const int* __restrict__ ed) {
    if (blockIdx.x >= HW_BLOCKS) {
        if (blockIdx.x == HW_BLOCKS && threadIdx.x == 0) g_scan_flag = 0;
        int gtid = (blockIdx.x - HW_BLOCKS) * 256 + threadIdx.x;  // < 10240
        const int4* ed4 = (const int4*)ed;
        for (int c = gtid; c < NE4; c += CNT_BLOCKS * 256) {
            int4 d4 = ed4[c];
            atomicAdd(&g_deg[d4.x], 1);
            atomicAdd(&g_deg[d4.y], 1);
            atomicAdd(&g_deg[d4.z], 1);
            atomicAdd(&g_deg[d4.w], 1);
        }
        return;
    }
    extern __shared__ char smem[];
    uint32_t uA = smem_u32_of(smem);           // h tile fp16 [m][k]
    uint32_t uB = uA + TILE_BYTES;             // W^T fp16 [n][k]
    __half* Bt = (__half*)(smem + TILE_BYTES);
    int tid = threadIdx.x;
    int row0 = blockIdx.x * 128;

    #pragma unroll
    for (int it = 0; it < 8; ++it) {
        int chunk = it * 256 + tid;
        int row = chunk >> 4, c8 = chunk & 15;
        int m = row0 + row;
        float4 v0 = make_float4(0.f, 0.f, 0.f, 0.f), v1 = v0;
        if (m < NN) {
            const float* p = h + (size_t)m * NH + c8 * 8;
            v0 = *(const float4*)p;
            v1 = *(const float4*)(p + 4);
        }
        __half2* dst = (__half2*)(smem + row * RS + c8 * 16);
        dst[0] = __floats2half2_rn(v0.x, v0.y);
        dst[1] = __floats2half2_rn(v0.z, v0.w);
        dst[2] = __floats2half2_rn(v1.x, v1.y);
        dst[3] = __floats2half2_rn(v1.z, v1.w);
    }
    // W^T conversion: float4 loads (coalesced), 4 scalar STS each
    #pragma unroll 4
    for (int it = 0; it < 16; ++it) {
        int idx = it * 256 + tid;              // 4096 float4 chunks
        int k = idx >> 5;                      // 0..127
        int n4 = (idx & 31) << 2;              // 0..124
        float4 w = *(const float4*)&W[k * NH + n4];
        Bt[(n4 + 0) * XT_STRIDE + k] = __float2half_rn(w.x);
        Bt[(n4 + 1) * XT_STRIDE + k] = __float2half_rn(w.y);
        Bt[(n4 + 2) * XT_STRIDE + k] = __float2half_rn(w.z);
        Bt[(n4 + 3) * XT_STRIDE + k] = __float2half_rn(w.w);
    }
    __syncthreads();

    int lane = tid & 31, wid = tid >> 5;
    int wm = wid & 1, wn = wid >> 1;
    int frow = lane >> 2, fcol = 2 * (lane & 3);
    uint32_t laneA = (uint32_t)((lane & 15) * RS + (lane >> 4) * 16);
    uint32_t laneB = (uint32_t)((((lane >> 4) & 1) * 8 + (lane & 7)) * RS
                                + ((lane >> 3) & 1) * 16);
    float acc[4][4][4] = {};
    #pragma unroll
    for (int k0 = 0; k0 < 8; ++k0) {
        uint32_t kb = k0 * 32;
        uint32_t bf[2][4];
        #pragma unroll
        for (int jp = 0; jp < 2; ++jp)
            ldsm_x4(bf[jp], uB + laneB + (uint32_t)((wn * 32 + jp * 16) * RS) + kb);
        #pragma unroll
        for (int i = 0; i < 4; ++i) {
            uint32_t a[4];
            ldsm_x4(a, uA + laneA + (uint32_t)((wm * 64 + i * 16) * RS) + kb);
            #pragma unroll
            for (int jp = 0; jp < 2; ++jp) {
                mma_f32acc(acc[i][2 * jp],     a, bf[jp][0], bf[jp][1]);
                mma_f32acc(acc[i][2 * jp + 1], a, bf[jp][2], bf[jp][3]);
            }
        }
    }
    #pragma unroll
    for (int i = 0; i < 4; ++i) {
        int rr = wm * 64 + i * 16 + frow;
        int m1 = row0 + rr, m2 = m1 + 8;
        #pragma unroll
        for (int j = 0; j < 4; ++j) {
            int c = wn * 32 + j * 8 + fcol;
            if (m1 < NN)
                *(__half2*)&g_hw[(size_t)m1 * NH + c] =
                    __floats2half2_rn(acc[i][j][0], acc[i][j][1]);
            if (m2 < NN)
                *(__half2*)&g_hw[(size_t)m2 * NH + c] =
                    __floats2half2_rn(acc[i][j][2], acc[i][j][3]);
        }
    }
}

// ============================================================================
// fused scan (block 0) + fill (all blocks, acquire-spin)
extern "C" __global__ void __launch_bounds__(256)
scan_fill_kernel(const int* __restrict__ es, const int* __restrict__ ed) {
    int tid = threadIdx.x;
    if (blockIdx.x == 0) {
        __shared__ int part[256];
        int base = tid * 40;
        int s = 0;
        #pragma unroll
        for (int q = 0; q < 40; ++q) { int i = base + q; if (i < NN) s += g_deg[i]; }
        part[tid] = s;
        __syncthreads();
        #pragma unroll
        for (int off = 1; off < 256; off <<= 1) {
            int v = (tid >= off) ? part[tid - off] : 0;
            __syncthreads();
            part[tid] += v;
            __syncthreads();
        }
        int run = (tid == 0) ? 0 : part[tid - 1];
        #pragma unroll
        for (int q = 0; q < 40; ++q) {
            int i = base + q;
            if (i < NN) { g_off[i] = run; run += g_deg[i]; }
        }
        if (tid == 0) g_off[NN] = part[255];
        __threadfence();
        __syncthreads();
        if (tid == 0) atomicExch(&g_scan_flag, 1);
    } else {
        if (tid == 0) { while (atomicAdd(&g_scan_flag, 0) == 0) {} }
        __syncthreads();
        __threadfence();
    }
    int i = blockIdx.x * 256 + tid;
    if (i < NE4) {
        int4 s4 = ((const int4*)es)[i];
        int4 d4 = ((const int4*)ed)[i];
        int o0 = atomicSub(&g_deg[d4.x], 1);
        int o1 = atomicSub(&g_deg[d4.y], 1);
        int o2 = atomicSub(&g_deg[d4.z], 1);
        int o3 = atomicSub(&g_deg[d4.w], 1);
        g_csr[g_off[d4.x] + o0 - 1] = s4.x;
        g_csr[g_off[d4.y] + o1 - 1] = s4.y;
        g_csr[g_off[d4.z] + o2 - 1] = s4.z;
        g_csr[g_off[d4.w] + o3 - 1] = s4.w;
    }
}

// ============================================================================
// gather + bias + relu + fp16 quantize — 4-edge fp16 chains (issue diet v2)
extern "C" __global__ void __launch_bounds__(128)
gather_fuse_kernel(const float* __restrict__ b) {
    __shared__ float sred[4 * NH];
    int node = blockIdx.x;
    int tid = threadIdx.x;
    int quad = tid >> 5, lane = tid & 31;
    int c4 = lane << 2;

    if (node >= NN) {
        if (tid < NH) g_y[(size_t)node * NH + tid] = __float2half(0.0f);
        return;
    }
    int beg = g_off[node];
    int end = g_off[node + 1];
    int total = end - beg;
    int efull = beg + (total & ~15);     // multiple of 16 edges handled 4/quad

    float4 a4 = make_float4(0.f, 0.f, 0.f, 0.f);
    // main loop: quad q takes contiguous edges [beg+16it+4q, +4)
    for (int e = beg + (quad << 2); e < efull; e += 16) {
        int s0 = g_csr[e],     s1 = g_csr[e + 1];
        int s2 = g_csr[e + 2], s3 = g_csr[e + 3];
        uint2 u0 = *(const uint2*)&g_hw[(size_t)s0 * NH + c4];
        uint2 u1 = *(const uint2*)&g_hw[(size_t)s1 * NH + c4];
        uint2 u2 = *(const uint2*)&g_hw[(size_t)s2 * NH + c4];
        uint2 u3 = *(const uint2*)&g_hw[(size_t)s3 * NH + c4];
        __half2 px = __hadd2(__hadd2(*(__half2*)&u0.x, *(__half2*)&u1.x),
                             __hadd2(*(__half2*)&u2.x, *(__half2*)&u3.x));
        __half2 py = __hadd2(__hadd2(*(__half2*)&u0.y, *(__half2*)&u1.y),
                             __hadd2(*(__half2*)&u2.y, *(__half2*)&u3.y));
        float2 f0 = __half22float2(px);
        float2 f1 = __half22float2(py);
        a4.x += f0.x; a4.y += f0.y; a4.z += f1.x; a4.w += f1.y;
    }
    // tail: single edges strided by quad
    for (int e = efull + quad; e < end; e += 4) {
        int s0 = g_csr[e];
        uint2 u0 = *(const uint2*)&g_hw[(size_t)s0 * NH + c4];
        float2 f0 = __half22float2(*(__half2*)&u0.x);
        float2 f1 = __half22float2(*(__half2*)&u0.y);
        a4.x += f0.x; a4.y += f0.y; a4.z += f1.x; a4.w += f1.y;
    }
    *(float4*)&sred[quad * NH + c4] = a4;
    __syncthreads();

    int c = tid;
    float v = sred[c] + sred[NH + c] + sred[2 * NH + c] + sred[3 * NH + c];
    v += b[c];
    v = v > 0.0f ? v : 0.0f;
    g_y[(size_t)node * NH + c] = __float2half_rn(v);
}

// ============================================================================
// xxt = y @ y^T — strip-persistent, FROZEN (at HBM write ceiling)
#define XXT_CTAS 296
#define T_TILES 3160

__device__ __forceinline__ void load_tile_async(const __half* __restrict__ src,
                                                int row0, uint32_t dst) {
    int tid = threadIdx.x;  // 256 threads, 8 x 16B each
    #pragma unroll
    for (int it = 0; it < 8; ++it) {
        int chunk = it * 256 + tid;
        int row = chunk >> 4, c16 = chunk & 15;
        cp16(dst + row * RS + c16 * 16,
             src + (size_t)(row0 + row) * NH + c16 * 8);
    }
}

extern "C" __global__ void __launch_bounds__(256, 2)
xxt_mma_kernel(float* __restrict__ out) {
    int g = blockIdx.x;
    int t0   = g * 10 + (g < 200 ? g : 200);
    int tend = t0 + (g < 200 ? 11 : 10);
    if (tend > T_TILES) tend = T_TILES;
    if (t0 >= tend) return;

    int r = (int)((159.0f - sqrtf(25281.0f - 8.0f * (float)t0)) * 0.5f);
    if (r < 0) r = 0; if (r > 78) r = 78;
    while ((r + 1) * 79 - ((r + 1) * r) / 2 <= t0) ++r;
    while (r * 79 - (r * (r - 1)) / 2 > t0) --r;
    int bym = r;
    int bxn = r + (t0 - (r * 79 - (r * (r - 1)) / 2));

    extern __shared__ char smem[];
    uint32_t uA = smem_u32_of(smem);

    int tid = threadIdx.x, lane = tid & 31, wid = tid >> 5;
    int wm = wid & 1, wn = wid >> 1;
    int frow = lane >> 2, fcol = 2 * (lane & 3);
    uint32_t laneA = (uint32_t)((lane & 15) * RS + (lane >> 4) * 16);
    uint32_t laneB = (uint32_t)((((lane >> 4) & 1) * 8 + (lane & 7)) * RS
                                + ((lane >> 3) & 1) * 16);

    bool diag = (bxn == bym);
    load_tile_async(g_y, bym * 128, uA);
    if (!diag) load_tile_async(g_y, bxn * 128, uA + TILE_BYTES * (1 + (t0 & 1)));
    CP_COMMIT(); CP_WAIT();
    __syncthreads();

    for (int t = t0; t < tend; ++t) {
        int bymN = bym, bxnN = bxn + 1;
        if (bxnN > 78) { bymN = bym + 1; bxnN = bymN; }
        bool can_pf = (t + 1 < tend) && (bymN == bym);
        if (can_pf) {
            load_tile_async(g_y, bxnN * 128, uA + TILE_BYTES * (1 + ((t + 1) & 1)));
            CP_COMMIT();
        }

        uint32_t uB = diag ? uA : (uA + TILE_BYTES * (1 + (t & 1)));

        float acc[4][4][4] = {};
        #pragma unroll
        for (int k0 = 0; k0 < 8; ++k0) {
            uint32_t kb = k0 * 32;
            uint32_t bf[2][4];
            #pragma unroll
            for (int jp = 0; jp < 2; ++jp)
                ldsm_x4(bf[jp], uB + laneB + (uint32_t)((wn * 32 + jp * 16) * RS) + kb);
            #pragma unroll
            for (int i = 0; i < 4; ++i) {
                uint32_t a[4];
                ldsm_x4(a, uA + laneA + (uint32_t)((wm * 64 + i * 16) * RS) + kb);
                #pragma unroll
                for (int jp = 0; jp < 2; ++jp) {
                    mma_f32acc(acc[i][2 * jp],     a, bf[jp][0], bf[jp][1]);
                    mma_f32acc(acc[i][2 * jp + 1], a, bf[jp][2], bf[jp][3]);
                }
            }
        }

        int m0 = bym * 128, n0 = bxn * 128;
        bool edge = (n0 + 127 >= NN) || (m0 + 127 >= NN);

        #pragma unroll
        for (int i = 0; i < 4; ++i) {
            int rr = wm * 64 + i * 16 + frow;
            #pragma unroll
            for (int j = 0; j < 4; ++j) {
                int c = wn * 32 + j * 8 + fcol;
                if (!edge) {
                    *(float2*)&out[(size_t)(m0 + rr) * NN + n0 + c] =
                        make_float2(acc[i][j][0], acc[i][j][1]);
                    *(float2*)&out[(size_t)(m0 + rr + 8) * NN + n0 + c] =
                        make_float2(acc[i][j][2], acc[i][j][3]);
                } else {
                    int m1 = m0 + rr, m2 = m0 + rr + 8, n = n0 + c;
                    if (m1 < NN) {
                        if (n < NN)     out[(size_t)m1 * NN + n]     = acc[i][j][0];
                        if (n + 1 < NN) out[(size_t)m1 * NN + n + 1] = acc[i][j][1];
                    }
                    if (m2 < NN) {
                        if (n < NN)     out[(size_t)m2 * NN + n]     = acc[i][j][2];
                        if (n + 1 < NN) out[(size_t)m2 * NN + n + 1] = acc[i][j][3];
                    }
                }
            }
        }
        if (!diag) {
            bool nedge = (n0 + 127 >= NN);
            #pragma unroll
            for (int i = 0; i < 4; ++i) {
                int rr = wm * 64 + i * 16 + frow;
                size_t m1 = (size_t)(m0 + rr);
                size_t m2 = (size_t)(m0 + rr + 8);
                #pragma unroll
                for (int j = 0; j < 4; ++j) {
                    int c = wn * 32 + j * 8 + fcol;
                    size_t n1 = (size_t)(n0 + c), n2 = (size_t)(n0 + c + 1);
                    if (!nedge) {
                        out[n1 * NN + m1] = acc[i][j][0];
                        out[n2 * NN + m1] = acc[i][j][1];
                        out[n1 * NN + m2] = acc[i][j][2];
                        out[n2 * NN + m2] = acc[i][j][3];
                    } else {
                        if (n1 < NN) { out[n1 * NN + m1] = acc[i][j][0];
                                       out[n1 * NN + m2] = acc[i][j][2]; }
                        if (n2 < NN) { out[n2 * NN + m1] = acc[i][j][1];
                                       out[n2 * NN + m2] = acc[i][j][3]; }
                    }
                }
            }
        }

        __syncthreads();
        if (t + 1 < tend) {
            if (!can_pf) {
                load_tile_async(g_y, bymN * 128, uA);
                CP_COMMIT();
            }
            CP_WAIT();
            __syncthreads();
        }
        bym = bymN; bxn = bxnN; diag = (bxnN == bymN);
    }
}

// ============================================================================
extern "C" void kernel_launch(void* const* d_in, const int* in_sizes, int n_in,
                              void* d_out, int out_size) {
    const float* h  = (const float*)d_in[0];
    const float* W  = (const float*)d_in[1];
    const float* b  = (const float*)d_in[2];
    const int*   es = (const int*)d_in[3];
    const int*   ed = (const int*)d_in[4];
    float*       out = (float*)d_out;

    cudaFuncSetAttribute(gemm_hw_count_kernel,
                         cudaFuncAttributeMaxDynamicSharedMemorySize, SMEM_2TILE);
    cudaFuncSetAttribute(xxt_mma_kernel,
                         cudaFuncAttributeMaxDynamicSharedMemorySize, SMEM_3TILE);

    gemm_hw_count_kernel<<<HW_BLOCKS + CNT_BLOCKS, 256, SMEM_2TILE>>>(h, W, ed);
    scan_fill_kernel<<<(NE4 + 255) / 256, 256>>>(es, ed);
    gather_fuse_kernel<<<NPAD, 128>>>(b);
    xxt_mma_kernel<<<XXT_CTAS, 256, SMEM_3TILE>>>(out);
}